// round 6
// baseline (speedup 1.0000x reference)
#include <cuda_runtime.h>
#include <math.h>
#include <stdint.h>

#define N_P   33600
#define NPAD  33792                 // 132 * 256
#define N_G   256
#define N_C   80
#define KK    13
#define LEN   16
#define NCHUNK 132
#define PPG   (NCHUNK * KK)         // 1716 partial entries per GT

typedef unsigned long long u64;
typedef unsigned int u32;

// ---------------- scratch (device globals; no runtime allocation) ----------
__device__ float  g_lT [(size_t)N_C * NPAD];  // logits, class-major
__device__ float4 g_pk0[NPAD];                // pred bbox x1,y1,x2,y2
__device__ float4 g_pk1[NPAD];                // px, py, 1/stride, +-area
__device__ float4 g_gtbox [N_G];
__device__ float4 g_gtmeta[N_G];              // area, cx, cy, pad
__device__ float4 g_vbox  [N_G];
__device__ int    g_glab  [N_G];
__device__ int    g_goff  [N_G];              // glab[j] * NPAD
__device__ int    g_cnt [N_P];
__device__ int    g_mgt [N_P];
__device__ float  g_piou[N_G * PPG];          // per-(GT,chunk) top-13 iou (desc)
__device__ u64    g_pkey[N_G * PPG];          // per-(GT,chunk) top-13 cost keys (asc)

// ---------------- fast approx intrinsics ------------------------------------
__device__ __forceinline__ float ex2a(float x){ float r; asm("ex2.approx.f32 %0,%1;" : "=f"(r) : "f"(x)); return r; }
__device__ __forceinline__ float lg2a(float x){ float r; asm("lg2.approx.f32 %0,%1;" : "=f"(r) : "f"(x)); return r; }
__device__ __forceinline__ float sqrta(float x){ float r; asm("sqrt.approx.f32 %0,%1;" : "=f"(r) : "f"(x)); return r; }
__device__ __forceinline__ float rcpa(float x){ float r; asm("rcp.approx.f32 %0,%1;" : "=f"(r) : "f"(x)); return r; }

// ---------------- math helpers (identical in pair & resolve) ----------------
__device__ __forceinline__ float iou_fast(float4 A, float Pw, float4 b, float area_b) {
    float area_a = fabsf(Pw);
    float ltx = fmaxf(A.x, b.x), lty = fmaxf(A.y, b.y);
    float rbx = fminf(A.z, b.z), rby = fminf(A.w, b.w);
    float w = fmaxf(rbx - ltx, 0.0f), h = fmaxf(rby - lty, 0.0f);
    float inter = w * h;
    float uni = (area_a + area_b) - inter;
    return inter * rcpa(fmaxf(uni, 1e-6f));
}

__device__ __forceinline__ float iou_exact(float4 A, float Pw, float4 b, float area_b) {
    float area_a = fabsf(Pw);
    float ltx = fmaxf(A.x, b.x), lty = fmaxf(A.y, b.y);
    float rbx = fminf(A.z, b.z), rby = fminf(A.w, b.w);
    float w = fmaxf(rbx - ltx, 0.0f), h = fmaxf(rby - lty, 0.0f);
    float inter = w * h;
    float uni = (area_a + area_b) - inter;
    return __fdiv_rn(inter, fmaxf(uni, 1e-6f));
}

// full cost from logit (sigmoid/softplus derived on the fly, same bits everywhere)
__device__ __forceinline__ float cost_full(float iou, float px, float py, float inv_st,
                                           float cx, float cy, float l) {
    float e   = ex2a(fabsf(l) * -1.4426950408889634f);
    float inv = rcpa(1.0f + e);
    float s   = (l >= 0.0f) ? inv : e * inv;
    float mm  = __fmaf_rn(lg2a(1.0f + e), 0.6931471805599453f, fmaxf(l, 0.0f));
    float dx = px - cx, dy = py - cy;
    float d2 = __fmaf_rn(dx, dx, dy * dy);
    float dist = sqrta(d2) * inv_st;
    float scp = ex2a(__fmaf_rn(dist, 3.321928094887362f, -9.965784284662087f));
    float d = iou - s;
    float scale = d * d;
    float bce = __fmaf_rn(-l, iou, mm);
    float ic = lg2a(iou + 1e-7f) * -2.0794415416798357f;
    return __fmaf_rn(bce, scale, ic + scp);
}

// ---------------- kernel G: GT preprocessing --------------------------------
__global__ void prep_gt_kernel(const float* __restrict__ gtb,
                               const int*   __restrict__ glab) {
    int j = threadIdx.x;
    if (j < N_G) {
        float x1 = gtb[j*4+0], y1 = gtb[j*4+1];
        float x2 = gtb[j*4+2], y2 = gtb[j*4+3];
        g_gtbox[j] = make_float4(x1, y1, x2, y2);
        float area = (x2 - x1) * (y2 - y1);
        bool pad = ((x1 + y1) + (x2 + y2)) > 0.0f;
        g_gtmeta[j] = make_float4(area, (x1 + x2) * 0.5f, (y1 + y2) * 0.5f,
                                  pad ? 1.0f : 0.0f);
        g_vbox[j] = pad ? make_float4(x1, y1, x2, y2)
                        : make_float4(1e30f, 1e30f, -1e30f, -1e30f);
        int lab = glab[j];
        g_glab[j] = lab;
        g_goff[j] = lab * NPAD;
    }
}

// ---------------- kernel L: transpose logits only ---------------------------
__global__ void __launch_bounds__(256) prep_logits_kernel(const float* __restrict__ ps) {
    __shared__ float sh[80][33];
    int tid = threadIdx.x;
    int i0 = blockIdx.x * 32;              // 33600/32 = 1050 exact
    const float* base = ps + (size_t)i0 * N_C;
    #pragma unroll
    for (int t = tid; t < 32 * 80; t += 256) {
        int il = t / 80;
        int c = t - il * 80;
        sh[c][il] = base[t];
    }
    __syncthreads();
    int il = tid & 31;
    int cb = tid >> 5;
    #pragma unroll
    for (int cc = cb; cc < 80; cc += 8)
        g_lT[cc * NPAD + i0 + il] = sh[cc][il];
}

// ---------------- kernel P: pack priors + valid mask + sentinels ------------
__global__ void __launch_bounds__(256) prep_priors_kernel(const float* __restrict__ priors,
                                                          const float* __restrict__ pb) {
    __shared__ float4 svb[N_G];
    int tid = threadIdx.x;
    svb[tid] = g_vbox[tid];
    __syncthreads();
    int i = blockIdx.x * 256 + tid;        // grid = 132 -> covers NPAD exactly
    if (i < N_P) {
        float4 PR = ((const float4*)priors)[i];
        float4 A  = ((const float4*)pb)[i];
        float px = PR.x, py = PR.y;
        bool any = false;
        for (int j = 0; j < N_G; j++) {
            float4 B = svb[j];
            if ((px > B.x) && (py > B.y) && (px < B.z) && (py < B.w)) { any = true; break; }
        }
        float area = (A.z - A.x) * (A.w - A.y);
        g_pk0[i] = A;
        g_pk1[i] = make_float4(px, py, rcpa(PR.z), any ? area : -area);
        g_cnt[i] = 0;
    } else {
        g_pk0[i] = make_float4(0.0f, 0.0f, 0.0f, 0.0f);   // degenerate -> iou 0
        g_pk1[i] = make_float4(0.0f, 0.0f, 1.0f, -1.0f);  // invalid -> cost 1e8
    }
}

// ---------------- lane-local sorted-8 inserts --------------------------------
__device__ __forceinline__ void ins8_iou(float* a, float v) {
    if (v > a[7]) {
        a[7] = v;
        #pragma unroll
        for (int k = 7; k > 0; k--)
            if (a[k] > a[k-1]) { float t = a[k-1]; a[k-1] = a[k]; a[k] = t; }
    }
}
__device__ __forceinline__ void ins8_key(u64* a, u64 v) {
    if (v < a[7]) {
        a[7] = v;
        #pragma unroll
        for (int k = 7; k > 0; k--)
            if (a[k] < a[k-1]) { u64 t = a[k-1]; a[k-1] = a[k]; a[k] = t; }
    }
}

// ---------------- kernel F: fused pairwise + per-(GT,chunk) top-13 ----------
__global__ void __launch_bounds__(256) pair_topk_kernel() {
    __shared__ float2 st[16][256];         // staged {iou,cost} for 16 GTs
    __shared__ float4 sb[32], sm[32];
    __shared__ int    soff[32];
    int tid = threadIdx.x;
    int chunk = blockIdx.x;                // 0..131
    int g0 = blockIdx.y * 32;
    if (tid < 32) {
        sb[tid]   = g_gtbox[g0 + tid];
        sm[tid]   = g_gtmeta[g0 + tid];
        soff[tid] = g_goff[g0 + tid];
    }
    __syncthreads();

    int i = chunk * 256 + tid;
    float4 A = g_pk0[i];
    float4 P = g_pk1[i];
    bool valid = P.w > 0.0f;

    int w = tid >> 5, lane = tid & 31;

    for (int stage = 0; stage < 2; stage++) {
        // ---- compute 16 GT columns for this chunk ----
        #pragma unroll 4
        for (int q = 0; q < 16; q++) {
            int jj = stage * 16 + q;
            float4 b  = sb[jj];
            float4 m4 = sm[jj];
            float iou = iou_fast(A, P.w, b, m4.x);
            float cost = 1e8f;
            if (valid) {
                float l = g_lT[soff[jj] + i];
                cost = cost_full(iou, P.x, P.y, P.z, m4.y, m4.z, l);
            }
            st[q][tid] = make_float2(iou, cost);
        }
        __syncthreads();

        // ---- each warp reduces 2 GTs: top-13 iou (desc) + top-13 cost keys (asc)
        for (int h = 0; h < 2; h++) {
            int q = 2 * w + h;
            int jglob = g0 + stage * 16 + q;

            float li[8]; u64 lk[8];
            #pragma unroll
            for (int k = 0; k < 8; k++) { li[k] = 0.0f; lk[k] = 0xFFFFFFFFFFFFFFFFull; }
            #pragma unroll
            for (int k = 0; k < 8; k++) {
                int idx = k * 32 + lane;
                float2 v = st[q][idx];
                ins8_iou(li, v.x);
                u64 key = (((u64)__float_as_uint(v.y)) << 32) | (u32)(chunk * 256 + idx);
                ins8_key(lk, key);
            }

            // 13 rounds: warp argmax iou via REDUX
            float myv = 0.0f;
            #pragma unroll
            for (int r = 0; r < KK; r++) {
                u32 hb = __float_as_uint(li[0]);          // iou >= 0 -> order-iso bits
                u32 mb = __reduce_max_sync(0xFFFFFFFFu, hb);
                if (lane == r) myv = __uint_as_float(mb);
                u32 ball = __ballot_sync(0xFFFFFFFFu, hb == mb);
                if (lane == (__ffs(ball) - 1)) {
                    #pragma unroll
                    for (int k = 0; k < 7; k++) li[k] = li[k+1];
                    li[7] = 0.0f;
                }
            }
            // 13 rounds: warp argmin (cost, index) via REDUX
            u64 myk = 0xFFFFFFFFFFFFFFFFull;
            #pragma unroll
            for (int r = 0; r < KK; r++) {
                u32 hc = (u32)(lk[0] >> 32);
                u32 hi = (u32)lk[0];
                u32 mc = __reduce_min_sync(0xFFFFFFFFu, hc);
                u32 cand = (hc == mc) ? hi : 0xFFFFFFFFu;
                u32 mi = __reduce_min_sync(0xFFFFFFFFu, cand);
                if (lane == r) myk = (((u64)mc) << 32) | mi;
                u32 ball = __ballot_sync(0xFFFFFFFFu, (hc == mc) && (hi == mi));
                if (lane == (__ffs(ball) - 1)) {
                    #pragma unroll
                    for (int k = 0; k < 7; k++) lk[k] = lk[k+1];
                    lk[7] = 0xFFFFFFFFFFFFFFFFull;
                }
            }
            if (lane < KK) {
                int base = jglob * PPG + chunk * KK + lane;
                g_piou[base] = myv;
                g_pkey[base] = myk;
            }
        }
        __syncthreads();
    }
}

// ---------------- bitonic LEN-16 merge machinery (phase 2) ------------------
__device__ __forceinline__ void merge_iou(float* a, const float* o) {
    float c[LEN];
    #pragma unroll
    for (int k = 0; k < LEN; k++) c[k] = fmaxf(a[k], o[LEN-1-k]);
    #pragma unroll
    for (int s = LEN/2; s > 0; s >>= 1) {
        #pragma unroll
        for (int k = 0; k < LEN; k++) {
            if ((k & s) == 0) {
                float lo = c[k], hi = c[k+s];
                c[k]   = fmaxf(lo, hi);
                c[k+s] = fminf(lo, hi);
            }
        }
    }
    #pragma unroll
    for (int k = 0; k < LEN; k++) a[k] = c[k];
}
__device__ __forceinline__ void merge_key(u64* a, const u64* o) {
    u64 c[LEN];
    #pragma unroll
    for (int k = 0; k < LEN; k++) {
        u64 x = a[k], y = o[LEN-1-k];
        c[k] = (x < y) ? x : y;
    }
    #pragma unroll
    for (int s = LEN/2; s > 0; s >>= 1) {
        #pragma unroll
        for (int k = 0; k < LEN; k++) {
            if ((k & s) == 0) {
                u64 lo = c[k], hi = c[k+s];
                u64 mn = (lo < hi) ? lo : hi;
                u64 mx = (lo < hi) ? hi : lo;
                c[k] = mn; c[k+s] = mx;
            }
        }
    }
    #pragma unroll
    for (int k = 0; k < LEN; k++) a[k] = c[k];
}
__device__ __forceinline__ void shfl_merge(u64* ck, float* vi, int off) {
    u64 ok[LEN]; float ovi[LEN];
    #pragma unroll
    for (int k = 0; k < LEN; k++) {
        ok [k] = __shfl_xor_sync(0xFFFFFFFFu, ck[k], off);
        ovi[k] = __shfl_xor_sync(0xFFFFFFFFu, vi[k], off);
    }
    merge_key(ck, ok);
    merge_iou(vi, ovi);
}
__device__ __forceinline__ void ins_iou(float* vi, float v) {
    vi[LEN-1] = v;
    #pragma unroll
    for (int k = LEN-1; k > 0; k--)
        if (vi[k] > vi[k-1]) { float t = vi[k-1]; vi[k-1] = vi[k]; vi[k] = t; }
}
__device__ __forceinline__ void ins_key(u64* ck, u64 key) {
    ck[LEN-1] = key;
    #pragma unroll
    for (int k = LEN-1; k > 0; k--)
        if (ck[k] < ck[k-1]) { u64 t = ck[k-1]; ck[k-1] = ck[k]; ck[k] = t; }
}

// ---------------- kernel M: per-GT merge of 132 partials + scatter ----------
__global__ void __launch_bounds__(256) topk_merge_kernel() {
    int j = blockIdx.x, tid = threadIdx.x;
    const float* __restrict__ pv = g_piou + j * PPG;
    const u64*   __restrict__ pk = g_pkey + j * PPG;

    float vi[LEN]; u64 ck[LEN];
    #pragma unroll
    for (int k = 0; k < LEN; k++) { vi[k] = 0.0f; ck[k] = 0xFFFFFFFFFFFFFFFFull; }

    for (int t = tid; t < PPG; t += 256) {
        float v = pv[t];
        if (v > vi[LEN-1]) ins_iou(vi, v);
        u64 key = pk[t];
        if (key < ck[LEN-1]) ins_key(ck, key);
    }

    #pragma unroll
    for (int off = 1; off < 32; off <<= 1) shfl_merge(ck, vi, off);

    __shared__ u64 s_ck[8][LEN]; __shared__ float s_vi[8][LEN];
    int w = tid >> 5, lane = tid & 31;
    if (lane == 0) {
        #pragma unroll
        for (int k = 0; k < LEN; k++) { s_ck[w][k] = ck[k]; s_vi[w][k] = vi[k]; }
    }
    __syncthreads();
    if (w == 0) {
        if (lane < 8) {
            #pragma unroll
            for (int k = 0; k < LEN; k++) { ck[k] = s_ck[lane][k]; vi[k] = s_vi[lane][k]; }
        } else {
            #pragma unroll
            for (int k = 0; k < LEN; k++) { ck[k] = 0xFFFFFFFFFFFFFFFFull; vi[k] = 0.0f; }
        }
        shfl_merge(ck, vi, 1);
        shfl_merge(ck, vi, 2);
        shfl_merge(ck, vi, 4);
        if (lane == 0) {
            float sum = 0.0f;
            #pragma unroll
            for (int k = 0; k < KK; k++) sum += vi[k];   // descending order
            int ks = (int)sum;
            if (ks < 1)  ks = 1;
            if (ks > KK) ks = KK;
            #pragma unroll
            for (int k = 0; k < KK; k++) {
                if (k < ks) {
                    int i = (int)(ck[k] & 0xFFFFFFFFull);
                    if (i < N_P) {
                        atomicAdd(&g_cnt[i], 1);
                        g_mgt[i] = j;     // racy only when cnt>1 (recomputed below)
                    }
                }
            }
        }
    }
}

// ---------------- kernel R: resolve per-prior assignment --------------------
__global__ void __launch_bounds__(256) resolve_kernel(float* __restrict__ out) {
    int i = blockIdx.x * 256 + threadIdx.x;
    if (i >= N_P) return;
    float4 P = g_pk1[i];
    float4 A = g_pk0[i];
    bool valid = P.w > 0.0f;
    int c = g_cnt[i];
    int gsel = 0;
    bool fg = false;
    if (c == 1) {
        gsel = g_mgt[i];
        fg = true;
    } else if (c > 1) {
        fg = true;
        float best = 3.4e38f;
        for (int j = 0; j < N_G; j++) {
            float4 bb = g_gtbox[j]; float4 mm4 = g_gtmeta[j];
            float io = iou_fast(A, P.w, bb, mm4.x);
            float cj = 1e8f;
            if (valid) {
                float l = g_lT[g_goff[j] + i];
                cj = cost_full(io, P.x, P.y, P.z, mm4.y, mm4.z, l);
            }
            if (cj < best) { best = cj; gsel = j; }   // first-min -> lowest index
        }
    }
    float iou = 0.0f;
    if (fg) iou = iou_exact(A, P.w, g_gtbox[gsel], g_gtmeta[gsel].x);
    bool fin = fg && valid;
    out[i]           = fin ? (float)(gsel + 1)   : 0.0f;
    out[N_P + i]     = fin ? iou                 : -1e8f;
    out[2*N_P + i]   = fin ? (float)g_glab[gsel] : -1.0f;
}

// ---------------- launch ------------------------------------------------------
extern "C" void kernel_launch(void* const* d_in, const int* in_sizes, int n_in,
                              void* d_out, int out_size) {
    const float* pred_scores = (const float*)d_in[0];
    const float* priors      = (const float*)d_in[1];
    const float* pred_bboxes = (const float*)d_in[2];
    const float* gt_bboxes   = (const float*)d_in[3];
    const int*   gt_labels   = (const int*)  d_in[4];

    prep_gt_kernel<<<1, 256>>>(gt_bboxes, gt_labels);
    prep_logits_kernel<<<N_P / 32, 256>>>(pred_scores);
    prep_priors_kernel<<<NPAD / 256, 256>>>(priors, pred_bboxes);
    dim3 gF(NCHUNK, 8);
    pair_topk_kernel<<<gF, 256>>>();
    topk_merge_kernel<<<N_G, 256>>>();
    resolve_kernel<<<(N_P + 255) / 256, 256>>>((float*)d_out);
}

// round 8
// speedup vs baseline: 1.6747x; 1.6747x over previous
#include <cuda_runtime.h>
#include <math.h>
#include <stdint.h>

#define N_P   33600
#define NPAD  33792                 // 132 * 256
#define N_G   256
#define N_C   80
#define KK    13
#define NCHUNK 132
#define PPG   (NCHUNK * KK)         // 1716 partial entries per GT

typedef unsigned long long u64;
typedef unsigned int u32;

// ---------------- scratch (device globals; no runtime allocation) ----------
__device__ float  g_lT [(size_t)N_C * NPAD];  // logits, class-major
__device__ float4 g_pk0[NPAD];                // pred bbox x1,y1,x2,y2
__device__ float4 g_pk1[NPAD];                // px, py, 1/stride, +-area
__device__ float4 g_gtbox [N_G];
__device__ float4 g_gtmeta[N_G];              // area, cx, cy, pad
__device__ float4 g_vbox  [N_G];
__device__ int    g_glab  [N_G];
__device__ int    g_goff  [N_G];              // glab[j] * NPAD
__device__ int    g_cnt [N_P];
__device__ int    g_mgt [N_P];
__device__ u64    g_amin[NPAD];               // per-prior {costbits, j} argmin
__device__ float  g_piou[N_G * PPG];          // per-(GT,chunk) top-13 iou (desc)
__device__ u64    g_pkey[N_G * PPG];          // per-(GT,chunk) top-13 cost keys (asc)

// ---------------- fast approx intrinsics ------------------------------------
__device__ __forceinline__ float ex2a(float x){ float r; asm("ex2.approx.f32 %0,%1;" : "=f"(r) : "f"(x)); return r; }
__device__ __forceinline__ float lg2a(float x){ float r; asm("lg2.approx.f32 %0,%1;" : "=f"(r) : "f"(x)); return r; }
__device__ __forceinline__ float sqrta(float x){ float r; asm("sqrt.approx.f32 %0,%1;" : "=f"(r) : "f"(x)); return r; }
__device__ __forceinline__ float rcpa(float x){ float r; asm("rcp.approx.f32 %0,%1;" : "=f"(r) : "f"(x)); return r; }

// ---------------- math helpers (identical everywhere) -----------------------
__device__ __forceinline__ float iou_fast(float4 A, float Pw, float4 b, float area_b) {
    float area_a = fabsf(Pw);
    float ltx = fmaxf(A.x, b.x), lty = fmaxf(A.y, b.y);
    float rbx = fminf(A.z, b.z), rby = fminf(A.w, b.w);
    float w = fmaxf(rbx - ltx, 0.0f), h = fmaxf(rby - lty, 0.0f);
    float inter = w * h;
    float uni = (area_a + area_b) - inter;
    return inter * rcpa(fmaxf(uni, 1e-6f));
}

__device__ __forceinline__ float iou_exact(float4 A, float Pw, float4 b, float area_b) {
    float area_a = fabsf(Pw);
    float ltx = fmaxf(A.x, b.x), lty = fmaxf(A.y, b.y);
    float rbx = fminf(A.z, b.z), rby = fminf(A.w, b.w);
    float w = fmaxf(rbx - ltx, 0.0f), h = fmaxf(rby - lty, 0.0f);
    float inter = w * h;
    float uni = (area_a + area_b) - inter;
    return __fdiv_rn(inter, fmaxf(uni, 1e-6f));
}

__device__ __forceinline__ float cost_full(float iou, float px, float py, float inv_st,
                                           float cx, float cy, float l) {
    float e   = ex2a(fabsf(l) * -1.4426950408889634f);
    float inv = rcpa(1.0f + e);
    float s   = (l >= 0.0f) ? inv : e * inv;
    float mm  = __fmaf_rn(lg2a(1.0f + e), 0.6931471805599453f, fmaxf(l, 0.0f));
    float dx = px - cx, dy = py - cy;
    float d2 = __fmaf_rn(dx, dx, dy * dy);
    float dist = sqrta(d2) * inv_st;
    float scp = ex2a(__fmaf_rn(dist, 3.321928094887362f, -9.965784284662087f));
    float d = iou - s;
    float scale = d * d;
    float bce = __fmaf_rn(-l, iou, mm);
    float ic = lg2a(iou + 1e-7f) * -2.0794415416798357f;
    return __fmaf_rn(bce, scale, ic + scp);
}

// ---------------- kernel G: GT preprocessing --------------------------------
__global__ void prep_gt_kernel(const float* __restrict__ gtb,
                               const int*   __restrict__ glab) {
    int j = threadIdx.x;
    if (j < N_G) {
        float x1 = gtb[j*4+0], y1 = gtb[j*4+1];
        float x2 = gtb[j*4+2], y2 = gtb[j*4+3];
        g_gtbox[j] = make_float4(x1, y1, x2, y2);
        float area = (x2 - x1) * (y2 - y1);
        bool pad = ((x1 + y1) + (x2 + y2)) > 0.0f;
        g_gtmeta[j] = make_float4(area, (x1 + x2) * 0.5f, (y1 + y2) * 0.5f,
                                  pad ? 1.0f : 0.0f);
        g_vbox[j] = pad ? make_float4(x1, y1, x2, y2)
                        : make_float4(1e30f, 1e30f, -1e30f, -1e30f);
        int lab = glab[j];
        g_glab[j] = lab;
        g_goff[j] = lab * NPAD;
    }
}

// ---------------- kernel L: transpose logits ---------------------------------
__global__ void __launch_bounds__(256) prep_logits_kernel(const float* __restrict__ ps) {
    __shared__ float sh[80][33];
    int tid = threadIdx.x;
    int i0 = blockIdx.x * 32;
    const float* base = ps + (size_t)i0 * N_C;
    #pragma unroll
    for (int t = tid; t < 32 * 80; t += 256) {
        int il = t / 80;
        int c = t - il * 80;
        sh[c][il] = base[t];
    }
    __syncthreads();
    int il = tid & 31;
    int cb = tid >> 5;
    #pragma unroll
    for (int cc = cb; cc < 80; cc += 8)
        g_lT[cc * NPAD + i0 + il] = sh[cc][il];
}

// ---------------- kernel P: pack priors + valid mask + init ------------------
__global__ void __launch_bounds__(256) prep_priors_kernel(const float* __restrict__ priors,
                                                          const float* __restrict__ pb) {
    __shared__ float4 svb[N_G];
    int tid = threadIdx.x;
    svb[tid] = g_vbox[tid];
    __syncthreads();
    int i = blockIdx.x * 256 + tid;        // grid = 132 -> covers NPAD exactly
    if (i < N_P) {
        float4 PR = ((const float4*)priors)[i];
        float4 A  = ((const float4*)pb)[i];
        float px = PR.x, py = PR.y;
        bool any = false;
        for (int j = 0; j < N_G; j++) {
            float4 B = svb[j];
            if ((px > B.x) && (py > B.y) && (px < B.z) && (py < B.w)) { any = true; break; }
        }
        float area = (A.z - A.x) * (A.w - A.y);
        g_pk0[i] = A;
        g_pk1[i] = make_float4(px, py, rcpa(PR.z), any ? area : -area);
        g_cnt[i] = 0;
    } else {
        g_pk0[i] = make_float4(0.0f, 0.0f, 0.0f, 0.0f);   // degenerate -> iou 0
        g_pk1[i] = make_float4(0.0f, 0.0f, 1.0f, -1.0f);  // invalid -> cost 1e8
    }
    g_amin[i] = 0xFFFFFFFFFFFFFFFFull;
}

// ---------------- lane-local sorted-13 inserts --------------------------------
__device__ __forceinline__ void ins13_iou(float* a, float v) {
    if (v > a[KK-1]) {
        a[KK-1] = v;
        #pragma unroll
        for (int k = KK-1; k > 0; k--)
            if (a[k] > a[k-1]) { float t = a[k-1]; a[k-1] = a[k]; a[k] = t; }
    }
}
__device__ __forceinline__ void ins13_key(u64* a, u64 v) {
    if (v < a[KK-1]) {
        a[KK-1] = v;
        #pragma unroll
        for (int k = KK-1; k > 0; k--)
            if (a[k] < a[k-1]) { u64 t = a[k-1]; a[k-1] = a[k]; a[k] = t; }
    }
}

// interleaved 13-round warp extraction: top-13 iou (desc) + top-13 keys (asc)
// lane r ends with the r-th best in (myv, myk). li/lk are lane-local sorted lists.
__device__ __forceinline__ void warp_extract13(float* li, u64* lk,
                                               float& myv, u64& myk) {
    int lane = threadIdx.x & 31;
    myv = 0.0f; myk = 0xFFFFFFFFFFFFFFFFull;
    #pragma unroll
    for (int r = 0; r < KK; r++) {
        u32 hb = __float_as_uint(li[0]);              // iou >= 0, order-iso bits
        u32 hc = (u32)(lk[0] >> 32);
        u32 hi = (u32)lk[0];
        u32 mb = __reduce_max_sync(0xFFFFFFFFu, hb);
        u32 mc = __reduce_min_sync(0xFFFFFFFFu, hc);
        u32 cand = (hc == mc) ? hi : 0xFFFFFFFFu;
        u32 mi = __reduce_min_sync(0xFFFFFFFFu, cand);
        if (lane == r) {
            myv = __uint_as_float(mb);
            myk = (((u64)mc) << 32) | mi;
        }
        u32 ballv = __ballot_sync(0xFFFFFFFFu, hb == mb);
        if (lane == (__ffs(ballv) - 1)) {
            #pragma unroll
            for (int k = 0; k < KK-1; k++) li[k] = li[k+1];
            li[KK-1] = 0.0f;
        }
        u32 ballk = __ballot_sync(0xFFFFFFFFu, (hc == mc) && (hi == mi));
        if (lane == (__ffs(ballk) - 1)) {
            #pragma unroll
            for (int k = 0; k < KK-1; k++) lk[k] = lk[k+1];
            lk[KK-1] = 0xFFFFFFFFFFFFFFFFull;
        }
    }
}

// ---------------- kernel F: fused pairwise + per-(GT,chunk) top-13 ----------
__global__ void __launch_bounds__(256) pair_topk_kernel() {
    __shared__ float2 st[8][256];          // staged {iou,cost} for 8 GTs (16KB)
    __shared__ float4 sb[32], sm[32];
    __shared__ int    soff[32];
    int tid = threadIdx.x;
    int chunk = blockIdx.x;                // 0..131
    int g0 = blockIdx.y * 32;
    if (tid < 32) {
        sb[tid]   = g_gtbox[g0 + tid];
        sm[tid]   = g_gtmeta[g0 + tid];
        soff[tid] = g_goff[g0 + tid];
    }
    __syncthreads();

    int i = chunk * 256 + tid;
    float4 A = g_pk0[i];
    float4 P = g_pk1[i];
    bool valid = P.w > 0.0f;

    int w = tid >> 5, lane = tid & 31;
    float best_cb = 3.4e38f;
    int   best_j  = g0;

    for (int stage = 0; stage < 4; stage++) {
        // ---- compute 8 GT columns ----
        #pragma unroll
        for (int q = 0; q < 8; q++) {
            int jj = stage * 8 + q;
            float4 b  = sb[jj];
            float4 m4 = sm[jj];
            float iou = iou_fast(A, P.w, b, m4.x);
            float cost = 1e8f;
            if (valid) {
                float l = g_lT[soff[jj] + i];
                cost = cost_full(iou, P.x, P.y, P.z, m4.y, m4.z, l);
            }
            st[q][tid] = make_float2(iou, cost);
            if (cost < best_cb) { best_cb = cost; best_j = g0 + jj; }
        }
        __syncthreads();

        // ---- warp w reduces GT stage*8 + w ----
        {
            int jglob = g0 + stage * 8 + w;
            float li[KK]; u64 lk[KK];
            #pragma unroll
            for (int k = 0; k < KK; k++) { li[k] = 0.0f; lk[k] = 0xFFFFFFFFFFFFFFFFull; }
            #pragma unroll
            for (int k = 0; k < 8; k++) {
                int idx = k * 32 + lane;
                float2 v = st[w][idx];
                ins13_iou(li, v.x);
                u64 key = (((u64)__float_as_uint(v.y)) << 32) | (u32)(chunk * 256 + idx);
                ins13_key(lk, key);
            }
            float myv; u64 myk;
            warp_extract13(li, lk, myv, myk);
            if (lane < KK) {
                int base = jglob * PPG + chunk * KK + lane;
                g_piou[base] = myv;
                g_pkey[base] = myk;
            }
        }
        __syncthreads();
    }

    u64 akey = (((u64)__float_as_uint(best_cb)) << 32) | (u32)best_j;
    atomicMin(&g_amin[i], akey);
}

// ---------------- kernel M: warp-per-GT merge of 132 partials + scatter -----
__global__ void __launch_bounds__(256) topk_merge_kernel() {
    int tid = threadIdx.x;
    int w = tid >> 5, lane = tid & 31;
    int j = blockIdx.x * 8 + w;            // grid = 32 -> 256 GTs

    const float* __restrict__ pv = g_piou + j * PPG;
    const u64*   __restrict__ pk = g_pkey + j * PPG;

    float li[KK]; u64 lk[KK];
    #pragma unroll
    for (int k = 0; k < KK; k++) { li[k] = 0.0f; lk[k] = 0xFFFFFFFFFFFFFFFFull; }

    for (int t = lane; t < PPG; t += 32) {
        ins13_iou(li, pv[t]);
        ins13_key(lk, pk[t]);
    }

    float myv; u64 myk;
    warp_extract13(li, lk, myv, myk);

    // descending-order sequential sum of top-13 ious
    float sum = 0.0f;
    #pragma unroll
    for (int r = 0; r < KK; r++)
        sum += __shfl_sync(0xFFFFFFFFu, myv, r);
    int ks = (int)sum;
    if (ks < 1)  ks = 1;
    if (ks > KK) ks = KK;

    if (lane < ks) {
        int i = (int)(myk & 0xFFFFFFFFull);
        if (i < N_P) {
            atomicAdd(&g_cnt[i], 1);
            g_mgt[i] = j;                  // racy only when cnt>1
        }
    }
}

// ---------------- kernel R: resolve (loop-free) ------------------------------
__global__ void __launch_bounds__(256) resolve_kernel(float* __restrict__ out) {
    int i = blockIdx.x * 256 + threadIdx.x;
    if (i >= N_P) return;
    float4 P = g_pk1[i];
    float4 A = g_pk0[i];
    bool valid = P.w > 0.0f;
    int c = g_cnt[i];
    int gsel = 0;
    bool fg = false;
    if (c == 1) {
        gsel = g_mgt[i];
        fg = true;
    } else if (c > 1) {
        gsel = (int)(g_amin[i] & 0xFFFFFFFFull);   // global argmin, lowest-j ties
        fg = true;
    }
    float iou = 0.0f;
    if (fg) iou = iou_exact(A, P.w, g_gtbox[gsel], g_gtmeta[gsel].x);
    bool fin = fg && valid;
    out[i]           = fin ? (float)(gsel + 1)   : 0.0f;
    out[N_P + i]     = fin ? iou                 : -1e8f;
    out[2*N_P + i]   = fin ? (float)g_glab[gsel] : -1.0f;
}

// ---------------- launch ------------------------------------------------------
extern "C" void kernel_launch(void* const* d_in, const int* in_sizes, int n_in,
                              void* d_out, int out_size) {
    const float* pred_scores = (const float*)d_in[0];
    const float* priors      = (const float*)d_in[1];
    const float* pred_bboxes = (const float*)d_in[2];
    const float* gt_bboxes   = (const float*)d_in[3];
    const int*   gt_labels   = (const int*)  d_in[4];

    prep_gt_kernel<<<1, 256>>>(gt_bboxes, gt_labels);
    prep_logits_kernel<<<N_P / 32, 256>>>(pred_scores);
    prep_priors_kernel<<<NPAD / 256, 256>>>(priors, pred_bboxes);
    dim3 gF(NCHUNK, 8);
    pair_topk_kernel<<<gF, 256>>>();
    topk_merge_kernel<<<32, 256>>>();
    resolve_kernel<<<(N_P + 255) / 256, 256>>>((float*)d_out);
}

// round 9
// speedup vs baseline: 2.1597x; 1.2897x over previous
#include <cuda_runtime.h>
#include <math.h>
#include <stdint.h>

#define N_P   33600
#define NPAD  33792                 // 132 * 256
#define N_G   256
#define N_C   80
#define KK    13
#define NCHUNK 132
#define PPG   (NCHUNK * KK)         // 1716 partial entries per GT

typedef unsigned long long u64;
typedef unsigned int u32;

// ---------------- scratch (device globals; no runtime allocation) ----------
__device__ float  g_lT [(size_t)N_C * NPAD];  // logits, class-major
__device__ float4 g_pk0[NPAD];                // pred bbox x1,y1,x2,y2
__device__ float4 g_pk1[NPAD];                // px, py, 1/stride, +-area
__device__ float4 g_gtbox [N_G];
__device__ float4 g_gtmeta[N_G];              // area, cx, cy, pad
__device__ float4 g_vbox  [N_G];
__device__ int    g_glab  [N_G];
__device__ int    g_goff  [N_G];              // glab[j] * NPAD
__device__ int    g_cnt [N_P];
__device__ int    g_mgt [N_P];
__device__ u64    g_amin[NPAD];               // per-prior {costbits, j} argmin
__device__ float  g_piou[N_G * PPG];          // per-(GT,chunk) top-13 iou (desc)
__device__ u64    g_pkey[N_G * PPG];          // per-(GT,chunk) top-13 cost keys (asc)

// ---------------- fast approx intrinsics ------------------------------------
__device__ __forceinline__ float ex2a(float x){ float r; asm("ex2.approx.f32 %0,%1;" : "=f"(r) : "f"(x)); return r; }
__device__ __forceinline__ float lg2a(float x){ float r; asm("lg2.approx.f32 %0,%1;" : "=f"(r) : "f"(x)); return r; }
__device__ __forceinline__ float sqrta(float x){ float r; asm("sqrt.approx.f32 %0,%1;" : "=f"(r) : "f"(x)); return r; }
__device__ __forceinline__ float rcpa(float x){ float r; asm("rcp.approx.f32 %0,%1;" : "=f"(r) : "f"(x)); return r; }

// ---------------- math helpers (identical everywhere) -----------------------
__device__ __forceinline__ float iou_fast(float4 A, float Pw, float4 b, float area_b) {
    float area_a = fabsf(Pw);
    float ltx = fmaxf(A.x, b.x), lty = fmaxf(A.y, b.y);
    float rbx = fminf(A.z, b.z), rby = fminf(A.w, b.w);
    float w = fmaxf(rbx - ltx, 0.0f), h = fmaxf(rby - lty, 0.0f);
    float inter = w * h;
    float uni = (area_a + area_b) - inter;
    return inter * rcpa(fmaxf(uni, 1e-6f));
}

__device__ __forceinline__ float iou_exact(float4 A, float Pw, float4 b, float area_b) {
    float area_a = fabsf(Pw);
    float ltx = fmaxf(A.x, b.x), lty = fmaxf(A.y, b.y);
    float rbx = fminf(A.z, b.z), rby = fminf(A.w, b.w);
    float w = fmaxf(rbx - ltx, 0.0f), h = fmaxf(rby - lty, 0.0f);
    float inter = w * h;
    float uni = (area_a + area_b) - inter;
    return __fdiv_rn(inter, fmaxf(uni, 1e-6f));
}

__device__ __forceinline__ float cost_full(float iou, float px, float py, float inv_st,
                                           float cx, float cy, float l) {
    float e   = ex2a(fabsf(l) * -1.4426950408889634f);
    float inv = rcpa(1.0f + e);
    float s   = (l >= 0.0f) ? inv : e * inv;
    float mm  = __fmaf_rn(lg2a(1.0f + e), 0.6931471805599453f, fmaxf(l, 0.0f));
    float dx = px - cx, dy = py - cy;
    float d2 = __fmaf_rn(dx, dx, dy * dy);
    float dist = sqrta(d2) * inv_st;
    float scp = ex2a(__fmaf_rn(dist, 3.321928094887362f, -9.965784284662087f));
    float d = iou - s;
    float scale = d * d;
    float bce = __fmaf_rn(-l, iou, mm);
    float ic = lg2a(iou + 1e-7f) * -2.0794415416798357f;
    return __fmaf_rn(bce, scale, ic + scp);
}

// ---------------- sorting-network primitives --------------------------------
__device__ __forceinline__ void cs_f(float& a, float& b) {   // descending
    float lo = fmaxf(a, b), hi = fminf(a, b);
    a = lo; b = hi;
}
__device__ __forceinline__ void cs_k(u64& a, u64& b) {       // ascending
    u64 mn = (a < b) ? a : b;
    u64 mx = (a < b) ? b : a;
    a = mn; b = mx;
}
// Batcher odd-even mergesort, 8 elements, 19 comparators
__device__ __forceinline__ void sort8_f(float* a) {
    cs_f(a[0],a[1]); cs_f(a[2],a[3]); cs_f(a[4],a[5]); cs_f(a[6],a[7]);
    cs_f(a[0],a[2]); cs_f(a[1],a[3]); cs_f(a[4],a[6]); cs_f(a[5],a[7]);
    cs_f(a[1],a[2]); cs_f(a[5],a[6]);
    cs_f(a[0],a[4]); cs_f(a[1],a[5]); cs_f(a[2],a[6]); cs_f(a[3],a[7]);
    cs_f(a[2],a[4]); cs_f(a[3],a[5]);
    cs_f(a[1],a[2]); cs_f(a[3],a[4]); cs_f(a[5],a[6]);
}
__device__ __forceinline__ void sort8_k(u64* a) {
    cs_k(a[0],a[1]); cs_k(a[2],a[3]); cs_k(a[4],a[5]); cs_k(a[6],a[7]);
    cs_k(a[0],a[2]); cs_k(a[1],a[3]); cs_k(a[4],a[6]); cs_k(a[5],a[7]);
    cs_k(a[1],a[2]); cs_k(a[5],a[6]);
    cs_k(a[0],a[4]); cs_k(a[1],a[5]); cs_k(a[2],a[6]); cs_k(a[3],a[7]);
    cs_k(a[2],a[4]); cs_k(a[3],a[5]);
    cs_k(a[1],a[2]); cs_k(a[3],a[4]); cs_k(a[5],a[6]);
}
__device__ __forceinline__ void sort4_f(float* a) {
    cs_f(a[0],a[1]); cs_f(a[2],a[3]); cs_f(a[0],a[2]); cs_f(a[1],a[3]); cs_f(a[1],a[2]);
}
__device__ __forceinline__ void sort4_k(u64* a) {
    cs_k(a[0],a[1]); cs_k(a[2],a[3]); cs_k(a[0],a[2]); cs_k(a[1],a[3]); cs_k(a[1],a[2]);
}

// interleaved 13-round warp extraction from per-lane sorted lists of length L.
// lane r ends with the r-th best (myv desc iou, myk asc cost key).
template<int L>
__device__ __forceinline__ void warp_extract13(float* li, u64* lk,
                                               float& myv, u64& myk) {
    int lane = threadIdx.x & 31;
    myv = 0.0f; myk = 0xFFFFFFFFFFFFFFFFull;
    #pragma unroll
    for (int r = 0; r < KK; r++) {
        u32 hb = __float_as_uint(li[0]);              // iou >= 0, order-iso bits
        u32 hc = (u32)(lk[0] >> 32);
        u32 hi = (u32)lk[0];
        u32 mb = __reduce_max_sync(0xFFFFFFFFu, hb);
        u32 mc = __reduce_min_sync(0xFFFFFFFFu, hc);
        u32 cand = (hc == mc) ? hi : 0xFFFFFFFFu;
        u32 mi = __reduce_min_sync(0xFFFFFFFFu, cand);
        if (lane == r) {
            myv = __uint_as_float(mb);
            myk = (((u64)mc) << 32) | mi;
        }
        u32 ballv = __ballot_sync(0xFFFFFFFFu, hb == mb);
        if (lane == (__ffs(ballv) - 1)) {
            #pragma unroll
            for (int k = 0; k < L-1; k++) li[k] = li[k+1];
            li[L-1] = 0.0f;
        }
        u32 ballk = __ballot_sync(0xFFFFFFFFu, (hc == mc) && (hi == mi));
        if (lane == (__ffs(ballk) - 1)) {
            #pragma unroll
            for (int k = 0; k < L-1; k++) lk[k] = lk[k+1];
            lk[L-1] = 0xFFFFFFFFFFFFFFFFull;
        }
    }
}

// ---------------- kernel G: GT preprocessing --------------------------------
__global__ void prep_gt_kernel(const float* __restrict__ gtb,
                               const int*   __restrict__ glab) {
    int j = threadIdx.x;
    if (j < N_G) {
        float x1 = gtb[j*4+0], y1 = gtb[j*4+1];
        float x2 = gtb[j*4+2], y2 = gtb[j*4+3];
        g_gtbox[j] = make_float4(x1, y1, x2, y2);
        float area = (x2 - x1) * (y2 - y1);
        bool pad = ((x1 + y1) + (x2 + y2)) > 0.0f;
        g_gtmeta[j] = make_float4(area, (x1 + x2) * 0.5f, (y1 + y2) * 0.5f,
                                  pad ? 1.0f : 0.0f);
        g_vbox[j] = pad ? make_float4(x1, y1, x2, y2)
                        : make_float4(1e30f, 1e30f, -1e30f, -1e30f);
        int lab = glab[j];
        g_glab[j] = lab;
        g_goff[j] = lab * NPAD;
    }
}

// ---------------- kernel L: transpose logits ---------------------------------
__global__ void __launch_bounds__(256) prep_logits_kernel(const float* __restrict__ ps) {
    __shared__ float sh[80][33];
    int tid = threadIdx.x;
    int i0 = blockIdx.x * 32;
    const float* base = ps + (size_t)i0 * N_C;
    #pragma unroll
    for (int t = tid; t < 32 * 80; t += 256) {
        int il = t / 80;
        int c = t - il * 80;
        sh[c][il] = base[t];
    }
    __syncthreads();
    int il = tid & 31;
    int cb = tid >> 5;
    #pragma unroll
    for (int cc = cb; cc < 80; cc += 8)
        g_lT[cc * NPAD + i0 + il] = sh[cc][il];
}

// ---------------- kernel P: pack priors + valid mask + init ------------------
__global__ void __launch_bounds__(256) prep_priors_kernel(const float* __restrict__ priors,
                                                          const float* __restrict__ pb) {
    __shared__ float4 svb[N_G];
    int tid = threadIdx.x;
    svb[tid] = g_vbox[tid];
    __syncthreads();
    int i = blockIdx.x * 256 + tid;        // grid = 132 -> covers NPAD exactly
    if (i < N_P) {
        float4 PR = ((const float4*)priors)[i];
        float4 A  = ((const float4*)pb)[i];
        float px = PR.x, py = PR.y;
        bool any = false;
        for (int j = 0; j < N_G; j++) {
            float4 B = svb[j];
            if ((px > B.x) && (py > B.y) && (px < B.z) && (py < B.w)) { any = true; break; }
        }
        float area = (A.z - A.x) * (A.w - A.y);
        g_pk0[i] = A;
        g_pk1[i] = make_float4(px, py, rcpa(PR.z), any ? area : -area);
        g_cnt[i] = 0;
    } else {
        g_pk0[i] = make_float4(0.0f, 0.0f, 0.0f, 0.0f);   // degenerate -> iou 0
        g_pk1[i] = make_float4(0.0f, 0.0f, 1.0f, -1.0f);  // invalid -> cost 1e8
    }
    g_amin[i] = 0xFFFFFFFFFFFFFFFFull;
}

// ---------------- kernel F: fused pairwise + per-(GT,chunk) top-13 ----------
__global__ void __launch_bounds__(256) pair_topk_kernel() {
    __shared__ float2 st[8][256];          // staged {iou,cost} for 8 GTs (16KB)
    __shared__ float4 sb[32], sm[32];
    __shared__ int    soff[32];
    int tid = threadIdx.x;
    int chunk = blockIdx.x;                // 0..131
    int g0 = blockIdx.y * 32;
    if (tid < 32) {
        sb[tid]   = g_gtbox[g0 + tid];
        sm[tid]   = g_gtmeta[g0 + tid];
        soff[tid] = g_goff[g0 + tid];
    }
    __syncthreads();

    int i = chunk * 256 + tid;
    float4 A = g_pk0[i];
    float4 P = g_pk1[i];
    bool valid = P.w > 0.0f;

    int w = tid >> 5, lane = tid & 31;
    float best_cb = 3.4e38f;
    int   best_j  = g0;

    for (int stage = 0; stage < 4; stage++) {
        // ---- compute 8 GT columns ----
        #pragma unroll
        for (int q = 0; q < 8; q++) {
            int jj = stage * 8 + q;
            float4 b  = sb[jj];
            float4 m4 = sm[jj];
            float iou = iou_fast(A, P.w, b, m4.x);
            float cost = 1e8f;
            if (valid) {
                float l = g_lT[soff[jj] + i];
                cost = cost_full(iou, P.x, P.y, P.z, m4.y, m4.z, l);
            }
            st[q][tid] = make_float2(iou, cost);
            if (cost < best_cb) { best_cb = cost; best_j = g0 + jj; }
        }
        __syncthreads();

        // ---- warp w reduces GT stage*8 + w (sort-8 + REDUX extraction) ----
        {
            int jglob = g0 + stage * 8 + w;
            float li[8]; u64 lk[8];
            #pragma unroll
            for (int k = 0; k < 8; k++) {
                int idx = k * 32 + lane;
                float2 v = st[w][idx];
                li[k] = v.x;
                lk[k] = (((u64)__float_as_uint(v.y)) << 32) | (u32)(chunk * 256 + idx);
            }
            sort8_f(li);
            sort8_k(lk);
            float myv; u64 myk;
            warp_extract13<8>(li, lk, myv, myk);
            if (lane < KK) {
                int base = jglob * PPG + chunk * KK + lane;
                g_piou[base] = myv;
                g_pkey[base] = myk;
            }
        }
        __syncthreads();
    }

    u64 akey = (((u64)__float_as_uint(best_cb)) << 32) | (u32)best_j;
    atomicMin(&g_amin[i], akey);
}

// ---------------- kernel M: block-per-GT merge of 132 partials + scatter ----
__global__ void __launch_bounds__(256) topk_merge_kernel() {
    int j = blockIdx.x;                    // grid = 256 GTs
    int tid = threadIdx.x;
    int w = tid >> 5, lane = tid & 31;

    const float* __restrict__ pv = g_piou + j * PPG;
    const u64*   __restrict__ pk = g_pkey + j * PPG;

    // each thread reads up to 7 partial entries (7*256 = 1792 >= 1716)
    float li[8]; u64 lk[8];
    #pragma unroll
    for (int r = 0; r < 8; r++) {
        int t = tid + r * 256;
        bool ok = (r < 6) || (t < PPG);
        li[r] = ok ? pv[t] : 0.0f;
        lk[r] = ok ? pk[t] : 0xFFFFFFFFFFFFFFFFull;
    }
    sort8_f(li);
    sort8_k(lk);

    float myv; u64 myk;
    warp_extract13<8>(li, lk, myv, myk);

    // stash each warp's top-13 in shared
    __shared__ float s_v[8 * KK];
    __shared__ u64   s_k[8 * KK];
    if (lane < KK) {
        s_v[w * KK + lane] = myv;
        s_k[w * KK + lane] = myk;
    }
    __syncthreads();

    if (w == 0) {
        // 104 candidates; each lane takes up to 4, sort-4, extract-13
        float fi[4]; u64 fk[4];
        #pragma unroll
        for (int r = 0; r < 4; r++) {
            int t = lane + r * 32;
            bool ok = (t < 8 * KK);
            fi[r] = ok ? s_v[t] : 0.0f;
            fk[r] = ok ? s_k[t] : 0xFFFFFFFFFFFFFFFFull;
        }
        sort4_f(fi);
        sort4_k(fk);
        float gv; u64 gk;
        warp_extract13<4>(fi, fk, gv, gk);

        // descending-order sequential sum of top-13 ious
        float sum = 0.0f;
        #pragma unroll
        for (int r = 0; r < KK; r++)
            sum += __shfl_sync(0xFFFFFFFFu, gv, r);
        int ks = (int)sum;
        if (ks < 1)  ks = 1;
        if (ks > KK) ks = KK;

        if (lane < ks) {
            int i = (int)(gk & 0xFFFFFFFFull);
            if (i < N_P) {
                atomicAdd(&g_cnt[i], 1);
                g_mgt[i] = j;              // racy only when cnt>1
            }
        }
    }
}

// ---------------- kernel R: resolve (loop-free) ------------------------------
__global__ void __launch_bounds__(256) resolve_kernel(float* __restrict__ out) {
    int i = blockIdx.x * 256 + threadIdx.x;
    if (i >= N_P) return;
    float4 P = g_pk1[i];
    float4 A = g_pk0[i];
    bool valid = P.w > 0.0f;
    int c = g_cnt[i];
    int gsel = 0;
    bool fg = false;
    if (c == 1) {
        gsel = g_mgt[i];
        fg = true;
    } else if (c > 1) {
        gsel = (int)(g_amin[i] & 0xFFFFFFFFull);   // global argmin, lowest-j ties
        fg = true;
    }
    float iou = 0.0f;
    if (fg) iou = iou_exact(A, P.w, g_gtbox[gsel], g_gtmeta[gsel].x);
    bool fin = fg && valid;
    out[i]           = fin ? (float)(gsel + 1)   : 0.0f;
    out[N_P + i]     = fin ? iou                 : -1e8f;
    out[2*N_P + i]   = fin ? (float)g_glab[gsel] : -1.0f;
}

// ---------------- launch ------------------------------------------------------
extern "C" void kernel_launch(void* const* d_in, const int* in_sizes, int n_in,
                              void* d_out, int out_size) {
    const float* pred_scores = (const float*)d_in[0];
    const float* priors      = (const float*)d_in[1];
    const float* pred_bboxes = (const float*)d_in[2];
    const float* gt_bboxes   = (const float*)d_in[3];
    const int*   gt_labels   = (const int*)  d_in[4];

    prep_gt_kernel<<<1, 256>>>(gt_bboxes, gt_labels);
    prep_logits_kernel<<<N_P / 32, 256>>>(pred_scores);
    prep_priors_kernel<<<NPAD / 256, 256>>>(priors, pred_bboxes);
    dim3 gF(NCHUNK, 8);
    pair_topk_kernel<<<gF, 256>>>();
    topk_merge_kernel<<<N_G, 256>>>();
    resolve_kernel<<<(N_P + 255) / 256, 256>>>((float*)d_out);
}

// round 10
// speedup vs baseline: 2.7040x; 1.2520x over previous
#include <cuda_runtime.h>
#include <math.h>
#include <stdint.h>

#define N_P   33600
#define NPAD  33792                 // 132 * 256
#define N_G   256
#define N_C   80
#define KK    13
#define NCHUNK 132
#define CAPC  2048                  // cost-pool capacity per GT
#define CAPI  2048                  // iou-pool capacity per GT
#define COST_T 96.0f                // screening threshold (see analysis)
#define UMAX  0xFFFFFFFFFFFFFFFFull

typedef unsigned long long u64;
typedef unsigned int u32;

// ---------------- scratch (device globals; no runtime allocation) ----------
__device__ float  g_lT [(size_t)N_C * NPAD];  // logits, class-major
__device__ float4 g_pk0[NPAD];                // pred bbox x1,y1,x2,y2
__device__ float4 g_pk1[NPAD];                // px, py, 1/stride, +-area
__device__ int    g_cnt [N_P];
__device__ int    g_mgt [N_P];
__device__ u64    g_amin[NPAD];               // per-prior {costbits, j} argmin
__device__ int    g_icnt[N_G];
__device__ int    g_ccnt[N_G];
__device__ float  g_ipool[N_G * CAPI];        // iou>0 values
__device__ u64    g_cpool[N_G * CAPC];        // {costbits, prior idx} for cost<T

// ---------------- fast approx intrinsics ------------------------------------
__device__ __forceinline__ float ex2a(float x){ float r; asm("ex2.approx.f32 %0,%1;" : "=f"(r) : "f"(x)); return r; }
__device__ __forceinline__ float lg2a(float x){ float r; asm("lg2.approx.f32 %0,%1;" : "=f"(r) : "f"(x)); return r; }
__device__ __forceinline__ float sqrta(float x){ float r; asm("sqrt.approx.f32 %0,%1;" : "=f"(r) : "f"(x)); return r; }
__device__ __forceinline__ float rcpa(float x){ float r; asm("rcp.approx.f32 %0,%1;" : "=f"(r) : "f"(x)); return r; }

// ---------------- math helpers (identical everywhere) -----------------------
__device__ __forceinline__ float iou_fast(float4 A, float Pw, float4 b, float area_b) {
    float area_a = fabsf(Pw);
    float ltx = fmaxf(A.x, b.x), lty = fmaxf(A.y, b.y);
    float rbx = fminf(A.z, b.z), rby = fminf(A.w, b.w);
    float w = fmaxf(rbx - ltx, 0.0f), h = fmaxf(rby - lty, 0.0f);
    float inter = w * h;
    float uni = (area_a + area_b) - inter;
    return inter * rcpa(fmaxf(uni, 1e-6f));
}

__device__ __forceinline__ float iou_exact(float4 A, float Pw, float4 b, float area_b) {
    float area_a = fabsf(Pw);
    float ltx = fmaxf(A.x, b.x), lty = fmaxf(A.y, b.y);
    float rbx = fminf(A.z, b.z), rby = fminf(A.w, b.w);
    float w = fmaxf(rbx - ltx, 0.0f), h = fmaxf(rby - lty, 0.0f);
    float inter = w * h;
    float uni = (area_a + area_b) - inter;
    return __fdiv_rn(inter, fmaxf(uni, 1e-6f));
}

__device__ __forceinline__ float cost_full(float iou, float px, float py, float inv_st,
                                           float cx, float cy, float l) {
    float e   = ex2a(fabsf(l) * -1.4426950408889634f);
    float inv = rcpa(1.0f + e);
    float s   = (l >= 0.0f) ? inv : e * inv;
    float mm  = __fmaf_rn(lg2a(1.0f + e), 0.6931471805599453f, fmaxf(l, 0.0f));
    float dx = px - cx, dy = py - cy;
    float d2 = __fmaf_rn(dx, dx, dy * dy);
    float dist = sqrta(d2) * inv_st;
    float scp = ex2a(__fmaf_rn(dist, 3.321928094887362f, -9.965784284662087f));
    float d = iou - s;
    float scale = d * d;
    float bce = __fmaf_rn(-l, iou, mm);
    float ic = lg2a(iou + 1e-7f) * -2.0794415416798357f;
    return __fmaf_rn(bce, scale, ic + scp);
}

// ---------------- lane-local sorted-13 inserts -------------------------------
__device__ __forceinline__ void ins13_iou(float* a, float v) {
    if (v > a[KK-1]) {
        a[KK-1] = v;
        #pragma unroll
        for (int k = KK-1; k > 0; k--)
            if (a[k] > a[k-1]) { float t = a[k-1]; a[k-1] = a[k]; a[k] = t; }
    }
}
__device__ __forceinline__ void ins13_key(u64* a, u64 v) {
    if (v < a[KK-1]) {
        a[KK-1] = v;
        #pragma unroll
        for (int k = KK-1; k > 0; k--)
            if (a[k] < a[k-1]) { u64 t = a[k-1]; a[k-1] = a[k]; a[k] = t; }
    }
}

// interleaved 13-round warp extraction from per-lane sorted lists (length KK).
template<int L>
__device__ __forceinline__ void warp_extract13(float* li, u64* lk,
                                               float& myv, u64& myk) {
    int lane = threadIdx.x & 31;
    myv = 0.0f; myk = UMAX;
    #pragma unroll
    for (int r = 0; r < KK; r++) {
        u32 hb = __float_as_uint(li[0]);
        u32 hc = (u32)(lk[0] >> 32);
        u32 hi = (u32)lk[0];
        u32 mb = __reduce_max_sync(0xFFFFFFFFu, hb);
        u32 mc = __reduce_min_sync(0xFFFFFFFFu, hc);
        u32 cand = (hc == mc) ? hi : 0xFFFFFFFFu;
        u32 mi = __reduce_min_sync(0xFFFFFFFFu, cand);
        if (lane == r) {
            myv = __uint_as_float(mb);
            myk = (((u64)mc) << 32) | mi;
        }
        u32 ballv = __ballot_sync(0xFFFFFFFFu, hb == mb);
        if (lane == (__ffs(ballv) - 1)) {
            #pragma unroll
            for (int k = 0; k < L-1; k++) li[k] = li[k+1];
            li[L-1] = 0.0f;
        }
        u32 ballk = __ballot_sync(0xFFFFFFFFu, (hc == mc) && (hi == mi));
        if (lane == (__ffs(ballk) - 1)) {
            #pragma unroll
            for (int k = 0; k < L-1; k++) lk[k] = lk[k+1];
            lk[L-1] = UMAX;
        }
    }
}

// ---------------- kernel L: transpose logits ---------------------------------
__global__ void __launch_bounds__(256) prep_logits_kernel(const float* __restrict__ ps) {
    __shared__ float sh[80][33];
    int tid = threadIdx.x;
    int i0 = blockIdx.x * 32;
    const float* base = ps + (size_t)i0 * N_C;
    #pragma unroll
    for (int t = tid; t < 32 * 80; t += 256) {
        int il = t / 80;
        int c = t - il * 80;
        sh[c][il] = base[t];
    }
    __syncthreads();
    int il = tid & 31;
    int cb = tid >> 5;
    #pragma unroll
    for (int cc = cb; cc < 80; cc += 8)
        g_lT[cc * NPAD + i0 + il] = sh[cc][il];
}

// ---------------- kernel P: pack priors + valid mask + init ------------------
__global__ void __launch_bounds__(256) prep_priors_kernel(const float* __restrict__ priors,
                                                          const float* __restrict__ pb,
                                                          const float* __restrict__ gtb) {
    __shared__ float4 svb[N_G];
    int tid = threadIdx.x;
    {
        float4 B = ((const float4*)gtb)[tid];
        bool pad = ((B.x + B.y) + (B.z + B.w)) > 0.0f;
        svb[tid] = pad ? B : make_float4(1e30f, 1e30f, -1e30f, -1e30f);
    }
    if (blockIdx.x == 0) { g_icnt[tid] = 0; g_ccnt[tid] = 0; }
    __syncthreads();
    int i = blockIdx.x * 256 + tid;
    if (i < N_P) {
        float4 PR = ((const float4*)priors)[i];
        float4 A  = ((const float4*)pb)[i];
        float px = PR.x, py = PR.y;
        bool any = false;
        for (int j = 0; j < N_G; j++) {
            float4 B = svb[j];
            if ((px > B.x) && (py > B.y) && (px < B.z) && (py < B.w)) { any = true; break; }
        }
        float area = (A.z - A.x) * (A.w - A.y);
        g_pk0[i] = A;
        g_pk1[i] = make_float4(px, py, rcpa(PR.z), any ? area : -area);
        g_cnt[i] = 0;
    } else {
        g_pk0[i] = make_float4(0.0f, 0.0f, 0.0f, 0.0f);   // degenerate -> iou 0
        g_pk1[i] = make_float4(0.0f, 0.0f, 1.0f, -1.0f);  // invalid -> cost 1e8
    }
    g_amin[i] = UMAX;
}

// ---------------- kernel S: pairwise scan + filtered compaction --------------
__global__ void __launch_bounds__(256) pair_scan_kernel(const float* __restrict__ gtb,
                                                        const int*   __restrict__ glab) {
    __shared__ float4 sb[32];
    __shared__ float4 sm[32];       // area, cx, cy, unused
    __shared__ int    soff[32];
    int tid = threadIdx.x;
    int chunk = blockIdx.x;                // 0..131
    int g0 = blockIdx.y * 32;
    if (tid < 32) {
        int j = g0 + tid;
        float4 B = ((const float4*)gtb)[j];
        sb[tid] = B;
        sm[tid] = make_float4((B.z - B.x) * (B.w - B.y),
                              (B.x + B.z) * 0.5f, (B.y + B.w) * 0.5f, 0.0f);
        soff[tid] = glab[j] * NPAD;
    }
    __syncthreads();

    int i = chunk * 256 + tid;
    float4 A = g_pk0[i];
    float4 P = g_pk1[i];
    bool valid = P.w > 0.0f;
    int lane = tid & 31;
    u32 lt_mask = (1u << lane) - 1u;

    float best_cb = 3.4e38f;
    int   best_j  = g0;

    #pragma unroll 4
    for (int jj = 0; jj < 32; jj++) {
        int j = g0 + jj;
        float4 b  = sb[jj];
        float4 m4 = sm[jj];
        float iou = iou_fast(A, P.w, b, m4.x);
        float l = g_lT[soff[jj] + i];
        float cf = cost_full(iou, P.x, P.y, P.z, m4.y, m4.z, l);
        float cost = valid ? cf : 1e8f;
        if (cost < best_cb) { best_cb = cost; best_j = j; }

        // iou pool (iou > 0)
        bool pi = iou > 0.0f;
        u32 mi = __ballot_sync(0xFFFFFFFFu, pi);
        if (mi) {
            int leader = __ffs(mi) - 1;
            int base;
            if (lane == leader) base = atomicAdd(&g_icnt[j], __popc(mi));
            base = __shfl_sync(0xFFFFFFFFu, base, leader);
            if (pi) {
                int slot = base + __popc(mi & lt_mask);
                if (slot < CAPI) g_ipool[j * CAPI + slot] = iou;
            }
        }
        // cost pool (cost < T)
        bool pc = cost < COST_T;
        u32 mc = __ballot_sync(0xFFFFFFFFu, pc);
        if (mc) {
            int leader = __ffs(mc) - 1;
            int base;
            if (lane == leader) base = atomicAdd(&g_ccnt[j], __popc(mc));
            base = __shfl_sync(0xFFFFFFFFu, base, leader);
            if (pc) {
                int slot = base + __popc(mc & lt_mask);
                if (slot < CAPC)
                    g_cpool[j * CAPC + slot] =
                        (((u64)__float_as_uint(cost)) << 32) | (u32)i;
            }
        }
    }

    u64 akey = (((u64)__float_as_uint(best_cb)) << 32) | (u32)best_j;
    atomicMin(&g_amin[i], akey);
}

// ---------------- kernel M: per-GT exact top-13 from pools + scatter ---------
__global__ void __launch_bounds__(256) select_kernel(const float* __restrict__ gtb,
                                                     const int*   __restrict__ glab) {
    int j = blockIdx.x;
    int tid = threadIdx.x;
    int w = tid >> 5, lane = tid & 31;

    int cntI = g_icnt[j];
    int cntC = g_ccnt[j];
    bool fb = (cntC < KK) || (cntC > CAPC) || (cntI > CAPI);

    float li[KK]; u64 lk[KK];
    #pragma unroll
    for (int k = 0; k < KK; k++) { li[k] = 0.0f; lk[k] = UMAX; }

    if (!fb) {
        const float* ip = g_ipool + j * CAPI;
        const u64*   cp = g_cpool + j * CAPC;
        for (int t = tid; t < cntI; t += 256) ins13_iou(li, ip[t]);
        for (int t = tid; t < cntC; t += 256) ins13_key(lk, cp[t]);
    } else {
        // exact full-column rescan (correctness guarantee; ~never runs)
        float4 b = ((const float4*)gtb)[j];
        float area_b = (b.z - b.x) * (b.w - b.y);
        float cx = (b.x + b.z) * 0.5f, cy = (b.y + b.w) * 0.5f;
        int goff = glab[j] * NPAD;
        for (int t = tid; t < NPAD; t += 256) {
            float4 A = g_pk0[t];
            float4 P = g_pk1[t];
            float iou = iou_fast(A, P.w, b, area_b);
            float cost = 1e8f;
            if (P.w > 0.0f)
                cost = cost_full(iou, P.x, P.y, P.z, cx, cy, g_lT[goff + t]);
            ins13_iou(li, iou);
            ins13_key(lk, (((u64)__float_as_uint(cost)) << 32) | (u32)t);
        }
    }

    float myv; u64 myk;
    warp_extract13<KK>(li, lk, myv, myk);

    __shared__ float s_v[8 * KK];
    __shared__ u64   s_k[8 * KK];
    if (lane < KK) {
        s_v[w * KK + lane] = myv;
        s_k[w * KK + lane] = myk;
    }
    __syncthreads();

    if (w == 0) {
        float fi[KK]; u64 fk[KK];
        #pragma unroll
        for (int k = 0; k < KK; k++) { fi[k] = 0.0f; fk[k] = UMAX; }
        #pragma unroll
        for (int r = 0; r < 4; r++) {
            int t = lane + r * 32;
            if (t < 8 * KK) {
                ins13_iou(fi, s_v[t]);
                ins13_key(fk, s_k[t]);
            }
        }
        float gv; u64 gk;
        warp_extract13<KK>(fi, fk, gv, gk);

        // descending-order sequential sum of top-13 ious
        float sum = 0.0f;
        #pragma unroll
        for (int r = 0; r < KK; r++)
            sum += __shfl_sync(0xFFFFFFFFu, gv, r);
        int ks = (int)sum;
        if (ks < 1)  ks = 1;
        if (ks > KK) ks = KK;

        if (lane < ks) {
            int i = (int)(gk & 0xFFFFFFFFull);
            if (i < N_P) {
                atomicAdd(&g_cnt[i], 1);
                g_mgt[i] = j;              // racy only when cnt>1
            }
        }
    }
}

// ---------------- kernel R: resolve (loop-free) ------------------------------
__global__ void __launch_bounds__(256) resolve_kernel(const float* __restrict__ gtb,
                                                      const int*   __restrict__ glab,
                                                      float* __restrict__ out) {
    int i = blockIdx.x * 256 + threadIdx.x;
    if (i >= N_P) return;
    float4 P = g_pk1[i];
    float4 A = g_pk0[i];
    bool valid = P.w > 0.0f;
    int c = g_cnt[i];
    int gsel = 0;
    bool fg = false;
    if (c == 1) {
        gsel = g_mgt[i];
        fg = true;
    } else if (c > 1) {
        gsel = (int)(g_amin[i] & 0xFFFFFFFFull);   // global argmin, lowest-j ties
        fg = true;
    }
    float iou = 0.0f;
    if (fg) {
        float4 b = ((const float4*)gtb)[gsel];
        float area_b = (b.z - b.x) * (b.w - b.y);
        iou = iou_exact(A, P.w, b, area_b);
    }
    bool fin = fg && valid;
    out[i]           = fin ? (float)(gsel + 1)    : 0.0f;
    out[N_P + i]     = fin ? iou                  : -1e8f;
    out[2*N_P + i]   = fin ? (float)glab[gsel]    : -1.0f;
}

// ---------------- launch ------------------------------------------------------
extern "C" void kernel_launch(void* const* d_in, const int* in_sizes, int n_in,
                              void* d_out, int out_size) {
    const float* pred_scores = (const float*)d_in[0];
    const float* priors      = (const float*)d_in[1];
    const float* pred_bboxes = (const float*)d_in[2];
    const float* gt_bboxes   = (const float*)d_in[3];
    const int*   gt_labels   = (const int*)  d_in[4];

    prep_logits_kernel<<<N_P / 32, 256>>>(pred_scores);
    prep_priors_kernel<<<NPAD / 256, 256>>>(priors, pred_bboxes, gt_bboxes);
    dim3 gS(NCHUNK, 8);
    pair_scan_kernel<<<gS, 256>>>(gt_bboxes, gt_labels);
    select_kernel<<<N_G, 256>>>(gt_bboxes, gt_labels);
    resolve_kernel<<<NCHUNK, 256>>>(gt_bboxes, gt_labels, (float*)d_out);
}

// round 11
// speedup vs baseline: 2.7722x; 1.0252x over previous
#include <cuda_runtime.h>
#include <math.h>
#include <stdint.h>

#define N_P   33600
#define NPAD  33792                 // 132 * 256
#define N_G   256
#define N_C   80
#define KK    13
#define NCHUNK 132
#define NLBLK 1050                  // logit-transpose blocks (33600/32)
#define CAPC  2048                  // cost-pool capacity per GT
#define CAPI  4096                  // iou-pool capacity per GT (worst case ~3300)
#define COST_T 96.0f                // screening threshold: cost >= scp = 10^(dist-3)
#define UMAX  0xFFFFFFFFFFFFFFFFull

typedef unsigned long long u64;
typedef unsigned int u32;

// ---------------- scratch (device globals; no runtime allocation) ----------
__device__ float  g_lT [(size_t)N_C * NPAD];  // logits, class-major
__device__ float4 g_pk0[NPAD];                // pred bbox x1,y1,x2,y2
__device__ float4 g_pk1[NPAD];                // px, py, 1/stride, +-area
__device__ int    g_cnt [N_P];
__device__ int    g_mgt [N_P];
__device__ u64    g_amin[NPAD];               // per-prior {costbits, j} argmin
__device__ int    g_icnt[N_G];
__device__ int    g_ccnt[N_G];
__device__ float  g_ipool[N_G * CAPI];        // iou>0 values
__device__ u64    g_cpool[N_G * CAPC];        // {costbits, prior idx} for cost<T

// ---------------- fast approx intrinsics ------------------------------------
__device__ __forceinline__ float ex2a(float x){ float r; asm("ex2.approx.f32 %0,%1;" : "=f"(r) : "f"(x)); return r; }
__device__ __forceinline__ float lg2a(float x){ float r; asm("lg2.approx.f32 %0,%1;" : "=f"(r) : "f"(x)); return r; }
__device__ __forceinline__ float sqrta(float x){ float r; asm("sqrt.approx.f32 %0,%1;" : "=f"(r) : "f"(x)); return r; }
__device__ __forceinline__ float rcpa(float x){ float r; asm("rcp.approx.f32 %0,%1;" : "=f"(r) : "f"(x)); return r; }

// ---------------- math helpers (identical everywhere) -----------------------
__device__ __forceinline__ float iou_fast(float4 A, float Pw, float4 b, float area_b) {
    float area_a = fabsf(Pw);
    float ltx = fmaxf(A.x, b.x), lty = fmaxf(A.y, b.y);
    float rbx = fminf(A.z, b.z), rby = fminf(A.w, b.w);
    float w = fmaxf(rbx - ltx, 0.0f), h = fmaxf(rby - lty, 0.0f);
    float inter = w * h;
    float uni = (area_a + area_b) - inter;
    return inter * rcpa(fmaxf(uni, 1e-6f));
}

__device__ __forceinline__ float iou_exact(float4 A, float Pw, float4 b, float area_b) {
    float area_a = fabsf(Pw);
    float ltx = fmaxf(A.x, b.x), lty = fmaxf(A.y, b.y);
    float rbx = fminf(A.z, b.z), rby = fminf(A.w, b.w);
    float w = fmaxf(rbx - ltx, 0.0f), h = fmaxf(rby - lty, 0.0f);
    float inter = w * h;
    float uni = (area_a + area_b) - inter;
    return __fdiv_rn(inter, fmaxf(uni, 1e-6f));
}

__device__ __forceinline__ float cost_full(float iou, float px, float py, float inv_st,
                                           float cx, float cy, float l) {
    float e   = ex2a(fabsf(l) * -1.4426950408889634f);
    float inv = rcpa(1.0f + e);
    float s   = (l >= 0.0f) ? inv : e * inv;
    float mm  = __fmaf_rn(lg2a(1.0f + e), 0.6931471805599453f, fmaxf(l, 0.0f));
    float dx = px - cx, dy = py - cy;
    float d2 = __fmaf_rn(dx, dx, dy * dy);
    float dist = sqrta(d2) * inv_st;
    float scp = ex2a(__fmaf_rn(dist, 3.321928094887362f, -9.965784284662087f));
    float d = iou - s;
    float scale = d * d;
    float bce = __fmaf_rn(-l, iou, mm);
    float ic = lg2a(iou + 1e-7f) * -2.0794415416798357f;
    return __fmaf_rn(bce, scale, ic + scp);
}

// ---------------- lane-local sorted-13 inserts -------------------------------
__device__ __forceinline__ void ins13_iou(float* a, float v) {
    if (v > a[KK-1]) {
        a[KK-1] = v;
        #pragma unroll
        for (int k = KK-1; k > 0; k--)
            if (a[k] > a[k-1]) { float t = a[k-1]; a[k-1] = a[k]; a[k] = t; }
    }
}
__device__ __forceinline__ void ins13_key(u64* a, u64 v) {
    if (v < a[KK-1]) {
        a[KK-1] = v;
        #pragma unroll
        for (int k = KK-1; k > 0; k--)
            if (a[k] < a[k-1]) { u64 t = a[k-1]; a[k-1] = a[k]; a[k] = t; }
    }
}

// interleaved 13-round warp extraction from per-lane sorted lists (length L).
template<int L>
__device__ __forceinline__ void warp_extract13(float* li, u64* lk,
                                               float& myv, u64& myk) {
    int lane = threadIdx.x & 31;
    myv = 0.0f; myk = UMAX;
    #pragma unroll
    for (int r = 0; r < KK; r++) {
        u32 hb = __float_as_uint(li[0]);
        u32 hc = (u32)(lk[0] >> 32);
        u32 hi = (u32)lk[0];
        u32 mb = __reduce_max_sync(0xFFFFFFFFu, hb);
        u32 mc = __reduce_min_sync(0xFFFFFFFFu, hc);
        u32 cand = (hc == mc) ? hi : 0xFFFFFFFFu;
        u32 mi = __reduce_min_sync(0xFFFFFFFFu, cand);
        if (lane == r) {
            myv = __uint_as_float(mb);
            myk = (((u64)mc) << 32) | mi;
        }
        u32 ballv = __ballot_sync(0xFFFFFFFFu, hb == mb);
        if (lane == (__ffs(ballv) - 1)) {
            #pragma unroll
            for (int k = 0; k < L-1; k++) li[k] = li[k+1];
            li[L-1] = 0.0f;
        }
        u32 ballk = __ballot_sync(0xFFFFFFFFu, (hc == mc) && (hi == mi));
        if (lane == (__ffs(ballk) - 1)) {
            #pragma unroll
            for (int k = 0; k < L-1; k++) lk[k] = lk[k+1];
            lk[L-1] = UMAX;
        }
    }
}

// ---------------- kernel PR: fused logit transpose + prior pack --------------
__global__ void __launch_bounds__(256) prep_kernel(const float* __restrict__ ps,
                                                   const float* __restrict__ priors,
                                                   const float* __restrict__ pb,
                                                   const float* __restrict__ gtb) {
    int tid = threadIdx.x;
    if (blockIdx.x < NLBLK) {
        // ---- logit transpose tile ----
        __shared__ float sh[80][33];
        int i0 = blockIdx.x * 32;
        const float* base = ps + (size_t)i0 * N_C;
        #pragma unroll
        for (int t = tid; t < 32 * 80; t += 256) {
            int il = t / 80;
            int c = t - il * 80;
            sh[c][il] = base[t];
        }
        __syncthreads();
        int il = tid & 31;
        int cb = tid >> 5;
        #pragma unroll
        for (int cc = cb; cc < 80; cc += 8)
            g_lT[cc * NPAD + i0 + il] = sh[cc][il];
    } else {
        // ---- prior pack + valid mask + init ----
        __shared__ float4 svb[N_G];
        {
            float4 B = ((const float4*)gtb)[tid];
            bool pad = ((B.x + B.y) + (B.z + B.w)) > 0.0f;
            svb[tid] = pad ? B : make_float4(1e30f, 1e30f, -1e30f, -1e30f);
        }
        int pblk = blockIdx.x - NLBLK;
        if (pblk == 0) { g_icnt[tid] = 0; g_ccnt[tid] = 0; }
        __syncthreads();
        int i = pblk * 256 + tid;
        if (i < N_P) {
            float4 PR = ((const float4*)priors)[i];
            float4 A  = ((const float4*)pb)[i];
            float px = PR.x, py = PR.y;
            bool any = false;
            for (int j = 0; j < N_G; j++) {
                float4 B = svb[j];
                if ((px > B.x) && (py > B.y) && (px < B.z) && (py < B.w)) { any = true; break; }
            }
            float area = (A.z - A.x) * (A.w - A.y);
            g_pk0[i] = A;
            g_pk1[i] = make_float4(px, py, rcpa(PR.z), any ? area : -area);
            g_cnt[i] = 0;
        } else {
            g_pk0[i] = make_float4(0.0f, 0.0f, 0.0f, 0.0f);   // degenerate -> iou 0
            g_pk1[i] = make_float4(0.0f, 0.0f, 1.0f, -1.0f);  // invalid -> cost 1e8
        }
        g_amin[i] = UMAX;
    }
}

// ---------------- kernel S: pairwise scan + filtered compaction --------------
__global__ void __launch_bounds__(256) pair_scan_kernel(const float* __restrict__ gtb,
                                                        const int*   __restrict__ glab) {
    __shared__ float4 sb[32];
    __shared__ float4 sm[32];       // area, cx, cy, unused
    __shared__ int    soff[32];
    int tid = threadIdx.x;
    int chunk = blockIdx.x;                // 0..131
    int g0 = blockIdx.y * 32;
    if (tid < 32) {
        int j = g0 + tid;
        float4 B = ((const float4*)gtb)[j];
        sb[tid] = B;
        sm[tid] = make_float4((B.z - B.x) * (B.w - B.y),
                              (B.x + B.z) * 0.5f, (B.y + B.w) * 0.5f, 0.0f);
        soff[tid] = glab[j] * NPAD;
    }
    __syncthreads();

    int i = chunk * 256 + tid;
    float4 A = g_pk0[i];
    float4 P = g_pk1[i];
    bool valid = P.w > 0.0f;
    int lane = tid & 31;
    u32 lt_mask = (1u << lane) - 1u;

    float best_cb = 3.4e38f;
    int   best_j  = g0;

    #pragma unroll 4
    for (int jj = 0; jj < 32; jj++) {
        int j = g0 + jj;
        float4 b  = sb[jj];
        float4 m4 = sm[jj];
        float iou = iou_fast(A, P.w, b, m4.x);
        float l = g_lT[soff[jj] + i];
        float cf = cost_full(iou, P.x, P.y, P.z, m4.y, m4.z, l);
        float cost = valid ? cf : 1e8f;
        if (cost < best_cb) { best_cb = cost; best_j = j; }

        // iou pool (iou > 0)
        bool pi = iou > 0.0f;
        u32 mi = __ballot_sync(0xFFFFFFFFu, pi);
        if (mi) {
            int leader = __ffs(mi) - 1;
            int base;
            if (lane == leader) base = atomicAdd(&g_icnt[j], __popc(mi));
            base = __shfl_sync(0xFFFFFFFFu, base, leader);
            if (pi) {
                int slot = base + __popc(mi & lt_mask);
                if (slot < CAPI) g_ipool[j * CAPI + slot] = iou;
            }
        }
        // cost pool (cost < T)
        bool pc = cost < COST_T;
        u32 mc = __ballot_sync(0xFFFFFFFFu, pc);
        if (mc) {
            int leader = __ffs(mc) - 1;
            int base;
            if (lane == leader) base = atomicAdd(&g_ccnt[j], __popc(mc));
            base = __shfl_sync(0xFFFFFFFFu, base, leader);
            if (pc) {
                int slot = base + __popc(mc & lt_mask);
                if (slot < CAPC)
                    g_cpool[j * CAPC + slot] =
                        (((u64)__float_as_uint(cost)) << 32) | (u32)i;
            }
        }
    }

    u64 akey = (((u64)__float_as_uint(best_cb)) << 32) | (u32)best_j;
    atomicMin(&g_amin[i], akey);
}

// ---------------- kernel M: per-GT exact top-13 from pools + scatter ---------
__global__ void __launch_bounds__(256) select_kernel(const float* __restrict__ gtb,
                                                     const int*   __restrict__ glab) {
    int j = blockIdx.x;
    int tid = threadIdx.x;
    int w = tid >> 5, lane = tid & 31;

    int cntI = g_icnt[j];
    int cntC = g_ccnt[j];
    bool fb = (cntC < KK) || (cntC > CAPC) || (cntI > CAPI);

    float li[KK]; u64 lk[KK];
    #pragma unroll
    for (int k = 0; k < KK; k++) { li[k] = 0.0f; lk[k] = UMAX; }

    if (!fb) {
        const float* ip = g_ipool + j * CAPI;
        const u64*   cp = g_cpool + j * CAPC;
        for (int t = tid; t < cntI; t += 256) ins13_iou(li, ip[t]);
        for (int t = tid; t < cntC; t += 256) ins13_key(lk, cp[t]);
    } else {
        // exact full-column rescan (correctness guarantee; ~never runs)
        float4 b = ((const float4*)gtb)[j];
        float area_b = (b.z - b.x) * (b.w - b.y);
        float cx = (b.x + b.z) * 0.5f, cy = (b.y + b.w) * 0.5f;
        int goff = glab[j] * NPAD;
        for (int t = tid; t < NPAD; t += 256) {
            float4 A = g_pk0[t];
            float4 P = g_pk1[t];
            float iou = iou_fast(A, P.w, b, area_b);
            float cost = 1e8f;
            if (P.w > 0.0f)
                cost = cost_full(iou, P.x, P.y, P.z, cx, cy, g_lT[goff + t]);
            ins13_iou(li, iou);
            ins13_key(lk, (((u64)__float_as_uint(cost)) << 32) | (u32)t);
        }
    }

    float myv; u64 myk;
    warp_extract13<KK>(li, lk, myv, myk);

    __shared__ float s_v[8 * KK];
    __shared__ u64   s_k[8 * KK];
    if (lane < KK) {
        s_v[w * KK + lane] = myv;
        s_k[w * KK + lane] = myk;
    }
    __syncthreads();

    if (w == 0) {
        float fi[KK]; u64 fk[KK];
        #pragma unroll
        for (int k = 0; k < KK; k++) { fi[k] = 0.0f; fk[k] = UMAX; }
        #pragma unroll
        for (int r = 0; r < 4; r++) {
            int t = lane + r * 32;
            if (t < 8 * KK) {
                ins13_iou(fi, s_v[t]);
                ins13_key(fk, s_k[t]);
            }
        }
        float gv; u64 gk;
        warp_extract13<KK>(fi, fk, gv, gk);

        // descending-order sequential sum of top-13 ious
        float sum = 0.0f;
        #pragma unroll
        for (int r = 0; r < KK; r++)
            sum += __shfl_sync(0xFFFFFFFFu, gv, r);
        int ks = (int)sum;
        if (ks < 1)  ks = 1;
        if (ks > KK) ks = KK;

        if (lane < ks) {
            int i = (int)(gk & 0xFFFFFFFFull);
            if (i < N_P) {
                atomicAdd(&g_cnt[i], 1);
                g_mgt[i] = j;              // racy only when cnt>1
            }
        }
    }
}

// ---------------- kernel R: resolve (loop-free) ------------------------------
__global__ void __launch_bounds__(256) resolve_kernel(const float* __restrict__ gtb,
                                                      const int*   __restrict__ glab,
                                                      float* __restrict__ out) {
    int i = blockIdx.x * 256 + threadIdx.x;
    if (i >= N_P) return;
    float4 P = g_pk1[i];
    float4 A = g_pk0[i];
    bool valid = P.w > 0.0f;
    int c = g_cnt[i];
    int gsel = 0;
    bool fg = false;
    if (c == 1) {
        gsel = g_mgt[i];
        fg = true;
    } else if (c > 1) {
        gsel = (int)(g_amin[i] & 0xFFFFFFFFull);   // global argmin, lowest-j ties
        fg = true;
    }
    float iou = 0.0f;
    if (fg) {
        float4 b = ((const float4*)gtb)[gsel];
        float area_b = (b.z - b.x) * (b.w - b.y);
        iou = iou_exact(A, P.w, b, area_b);
    }
    bool fin = fg && valid;
    out[i]           = fin ? (float)(gsel + 1)    : 0.0f;
    out[N_P + i]     = fin ? iou                  : -1e8f;
    out[2*N_P + i]   = fin ? (float)glab[gsel]    : -1.0f;
}

// ---------------- launch ------------------------------------------------------
extern "C" void kernel_launch(void* const* d_in, const int* in_sizes, int n_in,
                              void* d_out, int out_size) {
    const float* pred_scores = (const float*)d_in[0];
    const float* priors      = (const float*)d_in[1];
    const float* pred_bboxes = (const float*)d_in[2];
    const float* gt_bboxes   = (const float*)d_in[3];
    const int*   gt_labels   = (const int*)  d_in[4];

    prep_kernel<<<NLBLK + NCHUNK, 256>>>(pred_scores, priors, pred_bboxes, gt_bboxes);
    dim3 gS(NCHUNK, 8);
    pair_scan_kernel<<<gS, 256>>>(gt_bboxes, gt_labels);
    select_kernel<<<N_G, 256>>>(gt_bboxes, gt_labels);
    resolve_kernel<<<NCHUNK, 256>>>(gt_bboxes, gt_labels, (float*)d_out);
}

// round 12
// speedup vs baseline: 2.8481x; 1.0274x over previous
#include <cuda_runtime.h>
#include <math.h>
#include <stdint.h>

#define N_P   33600
#define NPAD  33792                 // 132 * 256
#define N_G   256
#define N_C   80
#define KK    13
#define NCHUNK 132
#define CAPC  2048                  // cost-pool capacity per GT
#define CAPI  4096                  // iou-pool capacity per GT (worst case ~3300)
#define COST_T 96.0f                // screening threshold: cost >= scp - 3e-7
#define UMAX  0xFFFFFFFFFFFFFFFFull

typedef unsigned long long u64;
typedef unsigned int u32;

// ---------------- scratch (device globals; no runtime allocation) ----------
__device__ float4 g_pk0[NPAD];                // pred bbox x1,y1,x2,y2
__device__ float4 g_pk1[NPAD];                // px, py, 1/stride, +-area
__device__ int    g_cnt [N_P];
__device__ int    g_mgt [N_P];
__device__ u64    g_amin[NPAD];               // per-prior {costbits, j} argmin
__device__ int    g_icnt[N_G];
__device__ int    g_ccnt[N_G];
__device__ float  g_ipool[N_G * CAPI];        // iou>0 values
__device__ u64    g_cpool[N_G * CAPC];        // {costbits, prior idx} for cost<T

// ---------------- fast approx intrinsics ------------------------------------
__device__ __forceinline__ float ex2a(float x){ float r; asm("ex2.approx.f32 %0,%1;" : "=f"(r) : "f"(x)); return r; }
__device__ __forceinline__ float lg2a(float x){ float r; asm("lg2.approx.f32 %0,%1;" : "=f"(r) : "f"(x)); return r; }
__device__ __forceinline__ float sqrta(float x){ float r; asm("sqrt.approx.f32 %0,%1;" : "=f"(r) : "f"(x)); return r; }
__device__ __forceinline__ float rcpa(float x){ float r; asm("rcp.approx.f32 %0,%1;" : "=f"(r) : "f"(x)); return r; }

// ---------------- math helpers (identical everywhere) -----------------------
__device__ __forceinline__ float iou_fast(float4 A, float Pw, float4 b, float area_b) {
    float area_a = fabsf(Pw);
    float ltx = fmaxf(A.x, b.x), lty = fmaxf(A.y, b.y);
    float rbx = fminf(A.z, b.z), rby = fminf(A.w, b.w);
    float w = fmaxf(rbx - ltx, 0.0f), h = fmaxf(rby - lty, 0.0f);
    float inter = w * h;
    float uni = (area_a + area_b) - inter;
    return inter * rcpa(fmaxf(uni, 1e-6f));
}

__device__ __forceinline__ float iou_exact(float4 A, float Pw, float4 b, float area_b) {
    float area_a = fabsf(Pw);
    float ltx = fmaxf(A.x, b.x), lty = fmaxf(A.y, b.y);
    float rbx = fminf(A.z, b.z), rby = fminf(A.w, b.w);
    float w = fmaxf(rbx - ltx, 0.0f), h = fmaxf(rby - lty, 0.0f);
    float inter = w * h;
    float uni = (area_a + area_b) - inter;
    return __fdiv_rn(inter, fmaxf(uni, 1e-6f));
}

// soft-center term: 10^(dist-3); reused as lower bound AND as the scp addend
__device__ __forceinline__ float scp_of(float px, float py, float inv_st,
                                        float cx, float cy) {
    float dx = px - cx, dy = py - cy;
    float d2 = __fmaf_rn(dx, dx, dy * dy);
    float dist = sqrta(d2) * inv_st;
    return ex2a(__fmaf_rn(dist, 3.321928094887362f, -9.965784284662087f));
}

// rest of the cost given iou, scp, logit (bit-identical across all callers)
__device__ __forceinline__ float cost_rest(float iou, float scp, float l) {
    float e   = ex2a(fabsf(l) * -1.4426950408889634f);
    float inv = rcpa(1.0f + e);
    float s   = (l >= 0.0f) ? inv : e * inv;
    float mm  = __fmaf_rn(lg2a(1.0f + e), 0.6931471805599453f, fmaxf(l, 0.0f));
    float d = iou - s;
    float scale = d * d;
    float bce = __fmaf_rn(-l, iou, mm);
    float ic = lg2a(iou + 1e-7f) * -2.0794415416798357f;
    return __fmaf_rn(bce, scale, ic + scp);
}

// ---------------- lane-local sorted-13 inserts -------------------------------
__device__ __forceinline__ void ins13_iou(float* a, float v) {
    if (v > a[KK-1]) {
        a[KK-1] = v;
        #pragma unroll
        for (int k = KK-1; k > 0; k--)
            if (a[k] > a[k-1]) { float t = a[k-1]; a[k-1] = a[k]; a[k] = t; }
    }
}
__device__ __forceinline__ void ins13_key(u64* a, u64 v) {
    if (v < a[KK-1]) {
        a[KK-1] = v;
        #pragma unroll
        for (int k = KK-1; k > 0; k--)
            if (a[k] < a[k-1]) { u64 t = a[k-1]; a[k-1] = a[k]; a[k] = t; }
    }
}

// interleaved 13-round warp extraction from per-lane sorted lists (length L).
template<int L>
__device__ __forceinline__ void warp_extract13(float* li, u64* lk,
                                               float& myv, u64& myk) {
    int lane = threadIdx.x & 31;
    myv = 0.0f; myk = UMAX;
    #pragma unroll
    for (int r = 0; r < KK; r++) {
        u32 hb = __float_as_uint(li[0]);
        u32 hc = (u32)(lk[0] >> 32);
        u32 hi = (u32)lk[0];
        u32 mb = __reduce_max_sync(0xFFFFFFFFu, hb);
        u32 mc = __reduce_min_sync(0xFFFFFFFFu, hc);
        u32 cand = (hc == mc) ? hi : 0xFFFFFFFFu;
        u32 mi = __reduce_min_sync(0xFFFFFFFFu, cand);
        if (lane == r) {
            myv = __uint_as_float(mb);
            myk = (((u64)mc) << 32) | mi;
        }
        u32 ballv = __ballot_sync(0xFFFFFFFFu, hb == mb);
        if (lane == (__ffs(ballv) - 1)) {
            #pragma unroll
            for (int k = 0; k < L-1; k++) li[k] = li[k+1];
            li[L-1] = 0.0f;
        }
        u32 ballk = __ballot_sync(0xFFFFFFFFu, (hc == mc) && (hi == mi));
        if (lane == (__ffs(ballk) - 1)) {
            #pragma unroll
            for (int k = 0; k < L-1; k++) lk[k] = lk[k+1];
            lk[L-1] = UMAX;
        }
    }
}

// ---------------- kernel P: pack priors + valid mask + init ------------------
__global__ void __launch_bounds__(256) prep_kernel(const float* __restrict__ priors,
                                                   const float* __restrict__ pb,
                                                   const float* __restrict__ gtb) {
    __shared__ float4 svb[N_G];
    int tid = threadIdx.x;
    {
        float4 B = ((const float4*)gtb)[tid];
        bool pad = ((B.x + B.y) + (B.z + B.w)) > 0.0f;
        svb[tid] = pad ? B : make_float4(1e30f, 1e30f, -1e30f, -1e30f);
    }
    if (blockIdx.x == 0) { g_icnt[tid] = 0; g_ccnt[tid] = 0; }
    __syncthreads();
    int i = blockIdx.x * 256 + tid;
    if (i < N_P) {
        float4 PR = ((const float4*)priors)[i];
        float4 A  = ((const float4*)pb)[i];
        float px = PR.x, py = PR.y;
        bool any = false;
        for (int j = 0; j < N_G; j++) {
            float4 B = svb[j];
            if ((px > B.x) && (py > B.y) && (px < B.z) && (py < B.w)) { any = true; break; }
        }
        float area = (A.z - A.x) * (A.w - A.y);
        g_pk0[i] = A;
        g_pk1[i] = make_float4(px, py, rcpa(PR.z), any ? area : -area);
        g_cnt[i] = 0;
    } else {
        g_pk0[i] = make_float4(0.0f, 0.0f, 0.0f, 0.0f);   // degenerate -> iou 0
        g_pk1[i] = make_float4(0.0f, 0.0f, 1.0f, -1.0f);  // invalid
    }
    g_amin[i] = UMAX;
}

// ---------------- kernel S: lazy pairwise scan + filtered compaction ---------
__global__ void __launch_bounds__(256) pair_scan_kernel(const float* __restrict__ ps,
                                                        const float* __restrict__ gtb,
                                                        const int*   __restrict__ glab) {
    __shared__ float4 sb[32];
    __shared__ float4 sm[32];       // area, cx, cy, unused
    __shared__ int    slab[32];
    int tid = threadIdx.x;
    int chunk = blockIdx.x;                // 0..131
    int g0 = blockIdx.y * 32;
    if (tid < 32) {
        int j = g0 + tid;
        float4 B = ((const float4*)gtb)[j];
        sb[tid] = B;
        sm[tid] = make_float4((B.z - B.x) * (B.w - B.y),
                              (B.x + B.z) * 0.5f, (B.y + B.w) * 0.5f, 0.0f);
        slab[tid] = glab[j];
    }
    __syncthreads();

    int i = chunk * 256 + tid;
    float4 A = g_pk0[i];
    float4 P = g_pk1[i];
    bool valid = P.w > 0.0f;
    int lane = tid & 31;
    u32 lt_mask = (1u << lane) - 1u;
    const float* psrow = ps + (size_t)i * N_C;

    float best_cb = 3.4e38f;
    int   best_j  = g0;

    #pragma unroll 4
    for (int jj = 0; jj < 32; jj++) {
        int j = g0 + jj;
        float4 b  = sb[jj];
        float4 m4 = sm[jj];
        float iou = iou_fast(A, P.w, b, m4.x);

        // iou pool (iou > 0)
        bool pi = iou > 0.0f;
        u32 mi = __ballot_sync(0xFFFFFFFFu, pi);
        if (mi) {
            int leader = __ffs(mi) - 1;
            int base;
            if (lane == leader) base = atomicAdd(&g_icnt[j], __popc(mi));
            base = __shfl_sync(0xFFFFFFFFu, base, leader);
            if (pi) {
                int slot = base + __popc(mi & lt_mask);
                if (slot < CAPI) g_ipool[j * CAPI + slot] = iou;
            }
        }

        // lazy cost: lower bound scp decides if the expensive tail is needed
        float scp = scp_of(P.x, P.y, P.z, m4.y, m4.z);
        bool nf = valid && (scp < fmaxf(best_cb, COST_T) + 1.0f);
        bool pc = false;
        float cost = 1e8f;
        if (nf) {
            float l = __ldg(psrow + slab[jj]);
            cost = cost_rest(iou, scp, l);
            if (cost < best_cb) { best_cb = cost; best_j = j; }
            pc = cost < COST_T;
        }
        u32 mc = __ballot_sync(0xFFFFFFFFu, pc);
        if (mc) {
            int leader = __ffs(mc) - 1;
            int base;
            if (lane == leader) base = atomicAdd(&g_ccnt[j], __popc(mc));
            base = __shfl_sync(0xFFFFFFFFu, base, leader);
            if (pc) {
                int slot = base + __popc(mc & lt_mask);
                if (slot < CAPC)
                    g_cpool[j * CAPC + slot] =
                        (((u64)__float_as_uint(cost)) << 32) | (u32)i;
            }
        }
    }

    u64 akey = (valid && best_cb < 3.4e38f)
             ? ((((u64)__float_as_uint(best_cb)) << 32) | (u32)best_j)
             : ((((u64)__float_as_uint(1e8f)) << 32) | 0u);   // invalid: all costs 1e8 -> argmin j=0
    atomicMin(&g_amin[i], akey);
}

// ---------------- kernel M: per-GT exact top-13 from pools + scatter ---------
__global__ void __launch_bounds__(256) select_kernel(const float* __restrict__ ps,
                                                     const float* __restrict__ gtb,
                                                     const int*   __restrict__ glab) {
    int j = blockIdx.x;
    int tid = threadIdx.x;
    int w = tid >> 5, lane = tid & 31;

    int cntI = g_icnt[j];
    int cntC = g_ccnt[j];
    bool fb = (cntC < KK) || (cntC > CAPC) || (cntI > CAPI);

    float li[KK]; u64 lk[KK];
    #pragma unroll
    for (int k = 0; k < KK; k++) { li[k] = 0.0f; lk[k] = UMAX; }

    if (!fb) {
        const float* ip = g_ipool + j * CAPI;
        const u64*   cp = g_cpool + j * CAPC;
        for (int t = tid; t < cntI; t += 256) ins13_iou(li, ip[t]);
        for (int t = tid; t < cntC; t += 256) ins13_key(lk, cp[t]);
    } else {
        // exact full-column rescan (correctness guarantee; ~never runs)
        float4 b = ((const float4*)gtb)[j];
        float area_b = (b.z - b.x) * (b.w - b.y);
        float cx = (b.x + b.z) * 0.5f, cy = (b.y + b.w) * 0.5f;
        int lab = glab[j];
        for (int t = tid; t < NPAD; t += 256) {
            float4 A = g_pk0[t];
            float4 P = g_pk1[t];
            float iou = iou_fast(A, P.w, b, area_b);
            float cost = 1e8f;
            if (P.w > 0.0f) {
                float scp = scp_of(P.x, P.y, P.z, cx, cy);
                float l = __ldg(ps + (size_t)t * N_C + lab);
                cost = cost_rest(iou, scp, l);
            }
            ins13_iou(li, iou);
            ins13_key(lk, (((u64)__float_as_uint(cost)) << 32) | (u32)t);
        }
    }

    float myv; u64 myk;
    warp_extract13<KK>(li, lk, myv, myk);

    __shared__ float s_v[8 * KK];
    __shared__ u64   s_k[8 * KK];
    if (lane < KK) {
        s_v[w * KK + lane] = myv;
        s_k[w * KK + lane] = myk;
    }
    __syncthreads();

    if (w == 0) {
        float fi[KK]; u64 fk[KK];
        #pragma unroll
        for (int k = 0; k < KK; k++) { fi[k] = 0.0f; fk[k] = UMAX; }
        #pragma unroll
        for (int r = 0; r < 4; r++) {
            int t = lane + r * 32;
            if (t < 8 * KK) {
                ins13_iou(fi, s_v[t]);
                ins13_key(fk, s_k[t]);
            }
        }
        float gv; u64 gk;
        warp_extract13<KK>(fi, fk, gv, gk);

        // descending-order sequential sum of top-13 ious
        float sum = 0.0f;
        #pragma unroll
        for (int r = 0; r < KK; r++)
            sum += __shfl_sync(0xFFFFFFFFu, gv, r);
        int ks = (int)sum;
        if (ks < 1)  ks = 1;
        if (ks > KK) ks = KK;

        if (lane < ks) {
            int i = (int)(gk & 0xFFFFFFFFull);
            if (i < N_P) {
                atomicAdd(&g_cnt[i], 1);
                g_mgt[i] = j;              // racy only when cnt>1
            }
        }
    }
}

// ---------------- kernel R: resolve (loop-free) ------------------------------
__global__ void __launch_bounds__(256) resolve_kernel(const float* __restrict__ gtb,
                                                      const int*   __restrict__ glab,
                                                      float* __restrict__ out) {
    int i = blockIdx.x * 256 + threadIdx.x;
    if (i >= N_P) return;
    float4 P = g_pk1[i];
    float4 A = g_pk0[i];
    bool valid = P.w > 0.0f;
    int c = g_cnt[i];
    int gsel = 0;
    bool fg = false;
    if (c == 1) {
        gsel = g_mgt[i];
        fg = true;
    } else if (c > 1) {
        gsel = (int)(g_amin[i] & 0xFFFFFFFFull);   // global argmin, lowest-j ties
        fg = true;
    }
    float iou = 0.0f;
    if (fg) {
        float4 b = ((const float4*)gtb)[gsel];
        float area_b = (b.z - b.x) * (b.w - b.y);
        iou = iou_exact(A, P.w, b, area_b);
    }
    bool fin = fg && valid;
    out[i]           = fin ? (float)(gsel + 1)    : 0.0f;
    out[N_P + i]     = fin ? iou                  : -1e8f;
    out[2*N_P + i]   = fin ? (float)glab[gsel]    : -1.0f;
}

// ---------------- launch ------------------------------------------------------
extern "C" void kernel_launch(void* const* d_in, const int* in_sizes, int n_in,
                              void* d_out, int out_size) {
    const float* pred_scores = (const float*)d_in[0];
    const float* priors      = (const float*)d_in[1];
    const float* pred_bboxes = (const float*)d_in[2];
    const float* gt_bboxes   = (const float*)d_in[3];
    const int*   gt_labels   = (const int*)  d_in[4];

    prep_kernel<<<NCHUNK, 256>>>(priors, pred_bboxes, gt_bboxes);
    dim3 gS(NCHUNK, 8);
    pair_scan_kernel<<<gS, 256>>>(pred_scores, gt_bboxes, gt_labels);
    select_kernel<<<N_G, 256>>>(pred_scores, gt_bboxes, gt_labels);
    resolve_kernel<<<NCHUNK, 256>>>(gt_bboxes, gt_labels, (float*)d_out);
}